// round 1
// baseline (speedup 1.0000x reference)
#include <cuda_runtime.h>
#include <cuda_bf16.h>
#include <cstdint>

// ---------------------------------------------------------------------------
// Problem constants (shapes are fixed by the dataset; N/E re-derived at launch)
// ---------------------------------------------------------------------------
#define MAXN 100000
#define MAXF 128

// Scratch (device globals; no cudaMalloc allowed)
__device__ float g_bufA[(size_t)MAXN * MAXF];   // ping
__device__ float g_bufB[(size_t)MAXN * MAXF];   // pong
__device__ float g_dis[MAXN];
__device__ int   g_deg[MAXN];
__device__ float g_stats[2 * MAXF];             // [sum | sumsq]
__device__ float g_bnp[2 * MAXF];               // [scale | shift]

// ---------------------------------------------------------------------------
// Degree / normalization
// ---------------------------------------------------------------------------
__global__ void k_zero_int(int* p, int n) {
    int i = blockIdx.x * blockDim.x + threadIdx.x;
    if (i < n) p[i] = 0;
}
__global__ void k_zero_f(float* p, int n) {
    int i = blockIdx.x * blockDim.x + threadIdx.x;
    if (i < n) p[i] = 0.0f;
}
__global__ void k_count_deg(const int* __restrict__ ei, int* __restrict__ deg, int E) {
    int e = blockIdx.x * blockDim.x + threadIdx.x;
    if (e < E) atomicAdd(&deg[__ldg(ei + E + e)], 1);
}
__global__ void k_dis(const int* __restrict__ deg, float* __restrict__ dis, int N) {
    int i = blockIdx.x * blockDim.x + threadIdx.x;
    if (i < N) dis[i] = rsqrtf((float)deg[i] + 1.0f);
}

// ---------------------------------------------------------------------------
// SGEMM: C[M,BN] = A[M,K] @ B[K,BN].  BM=128, BK=32, 256 threads, 8xTN tiles.
// ---------------------------------------------------------------------------
template <int BN, int TN>
__global__ __launch_bounds__(256) void k_sgemm(
    const float* __restrict__ A, const float* __restrict__ B,
    float* __restrict__ C, int M, int K)
{
    constexpr int BM = 128, BK = 32, TM = 8;
    __shared__ float As[BK][BM];
    __shared__ float Bs[BK][BN];
    const int tid  = threadIdx.x;
    const int tcol = tid & 15;
    const int trow = tid >> 4;
    const int m0   = blockIdx.x * BM;

    float acc[TM][TN];
#pragma unroll
    for (int i = 0; i < TM; i++)
#pragma unroll
        for (int j = 0; j < TN; j++) acc[i][j] = 0.0f;

    for (int k0 = 0; k0 < K; k0 += BK) {
        // A tile: 128x32 -> transposed into As[k][m]
#pragma unroll
        for (int i = 0; i < 4; i++) {
            int f    = tid + i * 256;      // 0..1023
            int aRow = f >> 3;
            int aC4  = f & 7;
            float4 v = make_float4(0.f, 0.f, 0.f, 0.f);
            int gr = m0 + aRow;
            if (gr < M)
                v = *(const float4*)(A + (size_t)gr * K + k0 + aC4 * 4);
            As[aC4 * 4 + 0][aRow] = v.x;
            As[aC4 * 4 + 1][aRow] = v.y;
            As[aC4 * 4 + 2][aRow] = v.z;
            As[aC4 * 4 + 3][aRow] = v.w;
        }
        // B tile: 32xBN
        constexpr int BF4 = BK * BN / 4;
#pragma unroll
        for (int i = 0; i < BF4 / 256; i++) {
            int f    = tid + i * 256;
            int bRow = f / (BN / 4);
            int bC4  = f % (BN / 4);
            float4 v = *(const float4*)(B + (size_t)(k0 + bRow) * BN + bC4 * 4);
            *(float4*)&Bs[bRow][bC4 * 4] = v;
        }
        __syncthreads();

#pragma unroll
        for (int kk = 0; kk < BK; kk++) {
            float ra[TM], rb[TN];
#pragma unroll
            for (int i = 0; i < TM; i++) ra[i] = As[kk][trow * TM + i];
#pragma unroll
            for (int j = 0; j < TN; j++) rb[j] = Bs[kk][tcol * TN + j];
#pragma unroll
            for (int i = 0; i < TM; i++)
#pragma unroll
                for (int j = 0; j < TN; j++)
                    acc[i][j] = fmaf(ra[i], rb[j], acc[i][j]);
        }
        __syncthreads();
    }

#pragma unroll
    for (int i = 0; i < TM; i++) {
        int gm = m0 + trow * TM + i;
        if (gm >= M) break;
#pragma unroll
        for (int j = 0; j < TN; j += 4) {
            float4 v = make_float4(acc[i][j], acc[i][j + 1],
                                   (TN > 2 ? acc[i][(j + 2) % TN] : 0.f),
                                   (TN > 2 ? acc[i][(j + 3) % TN] : 0.f));
            if (TN >= 4) {
                *(float4*)(C + (size_t)gm * BN + tcol * TN + j) = v;
            } else {
                // TN == 2: two scalar stores
                C[(size_t)gm * BN + tcol * TN + 0] = acc[i][0];
                C[(size_t)gm * BN + tcol * TN + 1] = acc[i][1];
            }
        }
    }
}

// ---------------------------------------------------------------------------
// agg init: agg[i] = h[i] * dis[i]^2 + bias   (self-loop contribution + bias)
// ---------------------------------------------------------------------------
template <int F>
__global__ void k_self_init(const float* __restrict__ h, const float* __restrict__ dis,
                            const float* __restrict__ bias, float* __restrict__ agg, int N)
{
    constexpr int F4 = F / 4;
    int i4 = blockIdx.x * blockDim.x + threadIdx.x;
    if (i4 >= N * F4) return;
    int node = i4 / F4;
    int j    = i4 - node * F4;
    float d = __ldg(dis + node);
    float c = d * d;
    float4 hv = __ldg((const float4*)h + i4);
    float4 bv = __ldg((const float4*)bias + j);
    float4 r;
    r.x = fmaf(hv.x, c, bv.x);
    r.y = fmaf(hv.y, c, bv.y);
    r.z = fmaf(hv.z, c, bv.z);
    r.w = fmaf(hv.w, c, bv.w);
    ((float4*)agg)[i4] = r;
}

// ---------------------------------------------------------------------------
// Edge aggregation: agg[dst] += h[src] * dis[src]*dis[dst]
// One (F/4)-lane group per edge; vector red.global.add.v4.f32 per 16B.
// ---------------------------------------------------------------------------
template <int F>
__global__ __launch_bounds__(256) void k_edge_agg(
    const int* __restrict__ ei, const float* __restrict__ h,
    const float* __restrict__ dis, float* __restrict__ agg, int E)
{
    constexpr int LPE = F / 4;                 // lanes per edge
    unsigned t = blockIdx.x * 256u + threadIdx.x;
    unsigned eid = t / LPE;
    unsigned j   = t - eid * LPE;
    if (eid >= (unsigned)E) return;
    int src = __ldg(ei + eid);
    int dst = __ldg(ei + E + eid);
    float c = __ldg(dis + src) * __ldg(dis + dst);
    float4 hv = __ldg((const float4*)(h + (size_t)src * F) + j);
    float4 v;
    v.x = hv.x * c; v.y = hv.y * c; v.z = hv.z * c; v.w = hv.w * c;
    float* addr = agg + (size_t)dst * F + j * 4;
    asm volatile("red.global.add.v4.f32 [%0], {%1,%2,%3,%4};"
                 :: "l"(addr), "f"(v.x), "f"(v.y), "f"(v.z), "f"(v.w)
                 : "memory");
}

// ---------------------------------------------------------------------------
// BatchNorm: column sums / sumsq, then finalize, then apply + ReLU
// ---------------------------------------------------------------------------
template <int F>
__global__ void k_bn_stats(const float* __restrict__ x, float* __restrict__ stats, int N)
{
    int f = threadIdx.x;        // blockDim.x == F
    float s = 0.f, sq = 0.f;
    for (int i = blockIdx.x; i < N; i += gridDim.x) {
        float v = x[(size_t)i * F + f];
        s  += v;
        sq = fmaf(v, v, sq);
    }
    atomicAdd(&stats[f], s);
    atomicAdd(&stats[F + f], sq);
}

__global__ void k_bn_finalize(const float* __restrict__ stats,
                              const float* __restrict__ g, const float* __restrict__ bt,
                              float* __restrict__ bnp, int N, int F)
{
    int f = threadIdx.x;
    if (f >= F) return;
    float inv_n = 1.0f / (float)N;
    float mu  = stats[f] * inv_n;
    float var = stats[F + f] * inv_n - mu * mu;
    var = fmaxf(var, 0.0f);
    float sc = g[f] * rsqrtf(var + 1e-5f);
    bnp[f]     = sc;
    bnp[F + f] = bt[f] - mu * sc;
}

template <int F>
__global__ void k_bn_relu(const float* __restrict__ agg, const float* __restrict__ bnp,
                          float* __restrict__ out, int N)
{
    constexpr int F4 = F / 4;
    int i4 = blockIdx.x * blockDim.x + threadIdx.x;
    if (i4 >= N * F4) return;
    int j = i4 % F4;
    float4 sc = __ldg((const float4*)bnp + j);
    float4 sh = __ldg((const float4*)bnp + F4 + j);
    float4 v  = ((const float4*)agg)[i4];
    float4 r;
    r.x = fmaxf(fmaf(v.x, sc.x, sh.x), 0.0f);
    r.y = fmaxf(fmaf(v.y, sc.y, sh.y), 0.0f);
    r.z = fmaxf(fmaf(v.z, sc.z, sh.z), 0.0f);
    r.w = fmaxf(fmaf(v.w, sc.w, sh.w), 0.0f);
    ((float4*)out)[i4] = r;
}

// ---------------------------------------------------------------------------
// Final FC: out[i] = h3[i,:32] . Wfc + bfc     (warp per node)
// ---------------------------------------------------------------------------
__global__ void k_final_fc(const float* __restrict__ h, const float* __restrict__ W,
                           const float* __restrict__ b, float* __restrict__ out, int N)
{
    int lane = threadIdx.x & 31;
    int node = (blockIdx.x * blockDim.x + threadIdx.x) >> 5;
    if (node >= N) return;
    float v = h[(size_t)node * 32 + lane] * __ldg(W + lane);
#pragma unroll
    for (int o = 16; o; o >>= 1) v += __shfl_down_sync(0xFFFFFFFFu, v, o);
    if (lane == 0) out[node] = v + __ldg(b);
}

// ---------------------------------------------------------------------------
// Launch
// ---------------------------------------------------------------------------
static inline int cdiv(long long a, long long b) { return (int)((a + b - 1) / b); }

extern "C" void kernel_launch(void* const* d_in, const int* in_sizes, int n_in,
                              void* d_out, int out_size)
{
    const float* x   = (const float*)d_in[0];
    const int*   ei  = (const int*)d_in[1];
    const float* W1  = (const float*)d_in[2];
    const float* b1  = (const float*)d_in[3];
    const float* g1  = (const float*)d_in[4];
    const float* bt1 = (const float*)d_in[5];
    const float* W2  = (const float*)d_in[6];
    const float* b2  = (const float*)d_in[7];
    const float* g2  = (const float*)d_in[8];
    const float* bt2 = (const float*)d_in[9];
    const float* W3  = (const float*)d_in[10];
    const float* b3  = (const float*)d_in[11];
    const float* g3  = (const float*)d_in[12];
    const float* bt3 = (const float*)d_in[13];
    const float* Wfc = (const float*)d_in[14];
    const float* bfc = (const float*)d_in[15];
    float* out = (float*)d_out;

    const int N = in_sizes[0] / 256;
    const int E = in_sizes[1] / 2;

    float *bufA, *bufB, *dis, *stats, *bnp;
    int* deg;
    cudaGetSymbolAddress((void**)&bufA,  g_bufA);
    cudaGetSymbolAddress((void**)&bufB,  g_bufB);
    cudaGetSymbolAddress((void**)&dis,   g_dis);
    cudaGetSymbolAddress((void**)&deg,   g_deg);
    cudaGetSymbolAddress((void**)&stats, g_stats);
    cudaGetSymbolAddress((void**)&bnp,   g_bnp);

    // ---- degree / dis ----
    k_zero_int<<<cdiv(N, 256), 256>>>(deg, N);
    k_count_deg<<<cdiv(E, 256), 256>>>(ei, deg, E);
    k_dis<<<cdiv(N, 256), 256>>>(deg, dis, N);

    // ================= Layer 1: 256 -> 128 =================
    {
        constexpr int F = 128;
        k_sgemm<128, 8><<<cdiv(N, 128), 256>>>(x, W1, bufA, N, 256);
        k_self_init<F><<<cdiv((long long)N * (F / 4), 256), 256>>>(bufA, dis, b1, bufB, N);
        k_edge_agg<F><<<cdiv((long long)E * (F / 4), 256), 256>>>(ei, bufA, dis, bufB, E);
        k_zero_f<<<1, 256>>>(stats, 2 * F);
        k_bn_stats<F><<<512, F>>>(bufB, stats, N);
        k_bn_finalize<<<1, F>>>(stats, g1, bt1, bnp, N, F);
        k_bn_relu<F><<<cdiv((long long)N * (F / 4), 256), 256>>>(bufB, bnp, bufA, N);
    }
    // ================= Layer 2: 128 -> 64 =================
    {
        constexpr int F = 64;
        k_sgemm<64, 4><<<cdiv(N, 128), 256>>>(bufA, W2, bufB, N, 128);
        k_self_init<F><<<cdiv((long long)N * (F / 4), 256), 256>>>(bufB, dis, b2, bufA, N);
        k_edge_agg<F><<<cdiv((long long)E * (F / 4), 256), 256>>>(ei, bufB, dis, bufA, E);
        k_zero_f<<<1, 256>>>(stats, 2 * F);
        k_bn_stats<F><<<512, F>>>(bufA, stats, N);
        k_bn_finalize<<<1, F>>>(stats, g2, bt2, bnp, N, F);
        k_bn_relu<F><<<cdiv((long long)N * (F / 4), 256), 256>>>(bufA, bnp, bufB, N);
    }
    // ================= Layer 3: 64 -> 32 =================
    {
        constexpr int F = 32;
        k_sgemm<32, 2><<<cdiv(N, 128), 256>>>(bufB, W3, bufA, N, 64);
        k_self_init<F><<<cdiv((long long)N * (F / 4), 256), 256>>>(bufA, dis, b3, bufB, N);
        k_edge_agg<F><<<cdiv((long long)E * (F / 4), 256), 256>>>(ei, bufA, dis, bufB, E);
        k_zero_f<<<1, 256>>>(stats, 2 * F);
        k_bn_stats<F><<<512, F>>>(bufB, stats, N);
        k_bn_finalize<<<1, F>>>(stats, g3, bt3, bnp, N, F);
        k_bn_relu<F><<<cdiv((long long)N * (F / 4), 256), 256>>>(bufB, bnp, bufA, N);
    }
    // ================= Final FC: 32 -> 1 =================
    k_final_fc<<<cdiv((long long)N * 32, 256), 256>>>(bufA, Wfc, bfc, out, N);
}

// round 2
// speedup vs baseline: 1.6452x; 1.6452x over previous
#include <cuda_runtime.h>
#include <cuda_bf16.h>
#include <cstdint>

#define MAXN 100000
#define MAXE 3200000
#define MAXF 128

// Scratch (device globals; no cudaMalloc allowed)
__device__ float g_bufA[(size_t)MAXN * MAXF];
__device__ float g_bufB[(size_t)MAXN * MAXF];
__device__ float g_dis[MAXN];
__device__ int   g_deg[MAXN];
__device__ int   g_rowptr[MAXN + 1];
__device__ int   g_cursor[MAXN + 1];
__device__ int   g_bsum[256];
__device__ int   g_csr_src[MAXE];
__device__ float g_stats[2 * MAXF];
__device__ float g_bnp[2 * MAXF];

// ---------------------------------------------------------------------------
// Degree / normalization / CSR build
// ---------------------------------------------------------------------------
__global__ void k_zero_int(int* p, int n) {
    int i = blockIdx.x * blockDim.x + threadIdx.x;
    if (i < n) p[i] = 0;
}
__global__ void k_zero_f(float* p, int n) {
    int i = blockIdx.x * blockDim.x + threadIdx.x;
    if (i < n) p[i] = 0.0f;
}
__global__ void k_count_deg(const int* __restrict__ ei, int* __restrict__ deg, int E) {
    int e = blockIdx.x * blockDim.x + threadIdx.x;
    if (e < E) atomicAdd(&deg[__ldg(ei + E + e)], 1);
}
__global__ void k_dis(const int* __restrict__ deg, float* __restrict__ dis, int N) {
    int i = blockIdx.x * blockDim.x + threadIdx.x;
    if (i < N) dis[i] = rsqrtf((float)deg[i] + 1.0f);
}

// exclusive scan of deg -> rowptr (3-kernel scheme)
__global__ void k_scan_block(const int* __restrict__ deg, int* __restrict__ exc,
                             int* __restrict__ bsum, int N)
{
    __shared__ int sh[1024];
    int i = blockIdx.x * 1024 + threadIdx.x;
    int v = (i < N) ? deg[i] : 0;
    sh[threadIdx.x] = v;
    __syncthreads();
#pragma unroll
    for (int o = 1; o < 1024; o <<= 1) {
        int t = (threadIdx.x >= o) ? sh[threadIdx.x - o] : 0;
        __syncthreads();
        sh[threadIdx.x] += t;
        __syncthreads();
    }
    if (i < N) exc[i] = sh[threadIdx.x] - v;
    if (threadIdx.x == 1023) bsum[blockIdx.x] = sh[1023];
}
__global__ void k_scan_bsum(int* bsum, int nb)
{
    __shared__ int sh[256];
    int t = threadIdx.x;
    int v = (t < nb) ? bsum[t] : 0;
    sh[t] = v;
    __syncthreads();
#pragma unroll
    for (int o = 1; o < 256; o <<= 1) {
        int u = (t >= o) ? sh[t - o] : 0;
        __syncthreads();
        sh[t] += u;
        __syncthreads();
    }
    if (t < nb) bsum[t] = sh[t] - v;   // exclusive
}
__global__ void k_scan_add(int* __restrict__ exc, const int* __restrict__ bsum, int N)
{
    int i = blockIdx.x * blockDim.x + threadIdx.x;
    if (i < N) exc[i] += bsum[i >> 10];
}
__global__ void k_copy_int(int* __restrict__ d, const int* __restrict__ s, int n)
{
    int i = blockIdx.x * blockDim.x + threadIdx.x;
    if (i < n) d[i] = s[i];
}
__global__ void k_csr_scatter(const int* __restrict__ ei, int* __restrict__ cursor,
                              int* __restrict__ csr_src, int E)
{
    int e = blockIdx.x * blockDim.x + threadIdx.x;
    if (e >= E) return;
    int src = __ldg(ei + e);
    int dst = __ldg(ei + E + e);
    int pos = atomicAdd(&cursor[dst], 1);
    csr_src[pos] = src;
}

// ---------------------------------------------------------------------------
// SGEMM: C[M,BN] = A[M,K] @ B[K,BN]; optional fused BN+ReLU on A elements.
// BM=128, BK=32, 256 threads, 8xTN register tiles, float4 LDS.
// ---------------------------------------------------------------------------
template <int BN, int TN>
__global__ __launch_bounds__(256) void k_sgemm(
    const float* __restrict__ A, const float* __restrict__ B,
    float* __restrict__ C, int M, int K, const float* __restrict__ bnp)
{
    constexpr int BM = 128, BK = 32, TM = 8;
    __shared__ float As[BK][BM];
    __shared__ float Bs[BK][BN];
    const int tid  = threadIdx.x;
    const int tcol = tid & 15;
    const int trow = tid >> 4;
    const int m0   = blockIdx.x * BM;

    float acc[TM][TN];
#pragma unroll
    for (int i = 0; i < TM; i++)
#pragma unroll
        for (int j = 0; j < TN; j++) acc[i][j] = 0.0f;

    for (int k0 = 0; k0 < K; k0 += BK) {
#pragma unroll
        for (int i = 0; i < 4; i++) {
            int f    = tid + i * 256;
            int aRow = f >> 3;
            int aC4  = f & 7;
            float4 v = make_float4(0.f, 0.f, 0.f, 0.f);
            int gr = m0 + aRow;
            if (gr < M)
                v = *(const float4*)(A + (size_t)gr * K + k0 + aC4 * 4);
            if (bnp) {   // fused BN + ReLU on the previous layer's agg
                int kidx = k0 + aC4 * 4;
                float4 sc = *(const float4*)(bnp + kidx);
                float4 sh = *(const float4*)(bnp + K + kidx);
                v.x = fmaxf(fmaf(v.x, sc.x, sh.x), 0.f);
                v.y = fmaxf(fmaf(v.y, sc.y, sh.y), 0.f);
                v.z = fmaxf(fmaf(v.z, sc.z, sh.z), 0.f);
                v.w = fmaxf(fmaf(v.w, sc.w, sh.w), 0.f);
            }
            As[aC4 * 4 + 0][aRow] = v.x;
            As[aC4 * 4 + 1][aRow] = v.y;
            As[aC4 * 4 + 2][aRow] = v.z;
            As[aC4 * 4 + 3][aRow] = v.w;
        }
        constexpr int BF4 = BK * BN / 4;
#pragma unroll
        for (int i = 0; i < BF4 / 256; i++) {
            int f    = tid + i * 256;
            int bRow = f / (BN / 4);
            int bC4  = f % (BN / 4);
            *(float4*)&Bs[bRow][bC4 * 4] =
                *(const float4*)(B + (size_t)(k0 + bRow) * BN + bC4 * 4);
        }
        __syncthreads();

#pragma unroll
        for (int kk = 0; kk < BK; kk++) {
            float ra[TM], rb[TN];
            *(float4*)&ra[0] = *(const float4*)&As[kk][trow * TM];
            *(float4*)&ra[4] = *(const float4*)&As[kk][trow * TM + 4];
            if (TN % 4 == 0) {
#pragma unroll
                for (int j = 0; j < TN; j += 4)
                    *(float4*)&rb[j] = *(const float4*)&Bs[kk][tcol * TN + j];
            } else {
#pragma unroll
                for (int j = 0; j < TN; j++) rb[j] = Bs[kk][tcol * TN + j];
            }
#pragma unroll
            for (int i = 0; i < TM; i++)
#pragma unroll
                for (int j = 0; j < TN; j++)
                    acc[i][j] = fmaf(ra[i], rb[j], acc[i][j]);
        }
        __syncthreads();
    }

#pragma unroll
    for (int i = 0; i < TM; i++) {
        int gm = m0 + trow * TM + i;
        if (gm >= M) break;
        if (TN % 4 == 0) {
#pragma unroll
            for (int j = 0; j < TN; j += 4) {
                float4 v = make_float4(acc[i][j], acc[i][j + 1], acc[i][j + 2], acc[i][j + 3]);
                *(float4*)(C + (size_t)gm * BN + tcol * TN + j) = v;
            }
        } else {
#pragma unroll
            for (int j = 0; j < TN; j++)
                C[(size_t)gm * BN + tcol * TN + j] = acc[i][j];
        }
    }
}

// ---------------------------------------------------------------------------
// CSR gather aggregation (fused self-loop + bias):
//   agg[i] = dis[i] * sum_e dis[src]*h[src]  +  dis[i]^2 * h[i]  +  bias
// G = F/4 lanes per node, float4 per lane.
// ---------------------------------------------------------------------------
template <int F>
__global__ __launch_bounds__(256) void k_gather(
    const int* __restrict__ rowptr, const int* __restrict__ deg,
    const int* __restrict__ csr_src, const float* __restrict__ h,
    const float* __restrict__ dis, const float* __restrict__ bias,
    float* __restrict__ agg, int N)
{
    constexpr int G = F / 4;
    int t    = blockIdx.x * 256 + threadIdx.x;
    int node = t / G;
    int j    = t - node * G;
    if (node >= N) return;

    int start = __ldg(rowptr + node);
    int cnt   = __ldg(deg + node);

    float4 acc = make_float4(0.f, 0.f, 0.f, 0.f);
    int src = (cnt > 0) ? __ldg(csr_src + start) : 0;
    for (int p = 0; p < cnt; p++) {
        int nsrc = (p + 1 < cnt) ? __ldg(csr_src + start + p + 1) : 0;
        float w  = __ldg(dis + src);
        float4 hv = __ldg((const float4*)(h + (size_t)src * F) + j);
        acc.x = fmaf(w, hv.x, acc.x);
        acc.y = fmaf(w, hv.y, acc.y);
        acc.z = fmaf(w, hv.z, acc.z);
        acc.w = fmaf(w, hv.w, acc.w);
        src = nsrc;
    }
    float d  = __ldg(dis + node);
    float d2 = d * d;
    float4 hs = __ldg((const float4*)(h + (size_t)node * F) + j);
    float4 bv = __ldg((const float4*)bias + j);
    float4 r;
    r.x = fmaf(d, acc.x, fmaf(d2, hs.x, bv.x));
    r.y = fmaf(d, acc.y, fmaf(d2, hs.y, bv.y));
    r.z = fmaf(d, acc.z, fmaf(d2, hs.z, bv.z));
    r.w = fmaf(d, acc.w, fmaf(d2, hs.w, bv.w));
    ((float4*)agg)[(size_t)node * G + j] = r;
}

// ---------------------------------------------------------------------------
// BatchNorm stats / finalize
// ---------------------------------------------------------------------------
template <int F>
__global__ void k_bn_stats(const float* __restrict__ x, float* __restrict__ stats, int N)
{
    int f = threadIdx.x;
    float s = 0.f, sq = 0.f;
    for (int i = blockIdx.x; i < N; i += gridDim.x) {
        float v = x[(size_t)i * F + f];
        s += v;
        sq = fmaf(v, v, sq);
    }
    atomicAdd(&stats[f], s);
    atomicAdd(&stats[F + f], sq);
}

__global__ void k_bn_finalize(const float* __restrict__ stats,
                              const float* __restrict__ g, const float* __restrict__ bt,
                              float* __restrict__ bnp, int N, int F)
{
    int f = threadIdx.x;
    if (f >= F) return;
    float inv_n = 1.0f / (float)N;
    float mu  = stats[f] * inv_n;
    float var = fmaxf(stats[F + f] * inv_n - mu * mu, 0.0f);
    float sc = g[f] * rsqrtf(var + 1e-5f);
    bnp[f]     = sc;
    bnp[F + f] = bt[f] - mu * sc;
}

// ---------------------------------------------------------------------------
// Final FC with fused BN+ReLU: out[i] = relu(bn(h3[i,:])) . Wfc + bfc
// ---------------------------------------------------------------------------
__global__ void k_final_fc(const float* __restrict__ h, const float* __restrict__ bnp,
                           const float* __restrict__ W, const float* __restrict__ b,
                           float* __restrict__ out, int N)
{
    int lane = threadIdx.x & 31;
    int node = (blockIdx.x * blockDim.x + threadIdx.x) >> 5;
    if (node >= N) return;
    float sc = __ldg(bnp + lane);
    float sh = __ldg(bnp + 32 + lane);
    float v = fmaxf(fmaf(h[(size_t)node * 32 + lane], sc, sh), 0.0f) * __ldg(W + lane);
#pragma unroll
    for (int o = 16; o; o >>= 1) v += __shfl_down_sync(0xFFFFFFFFu, v, o);
    if (lane == 0) out[node] = v + __ldg(b);
}

// ---------------------------------------------------------------------------
static inline int cdiv(long long a, long long b) { return (int)((a + b - 1) / b); }

extern "C" void kernel_launch(void* const* d_in, const int* in_sizes, int n_in,
                              void* d_out, int out_size)
{
    const float* x   = (const float*)d_in[0];
    const int*   ei  = (const int*)d_in[1];
    const float* W1  = (const float*)d_in[2];
    const float* b1  = (const float*)d_in[3];
    const float* g1  = (const float*)d_in[4];
    const float* bt1 = (const float*)d_in[5];
    const float* W2  = (const float*)d_in[6];
    const float* b2  = (const float*)d_in[7];
    const float* g2  = (const float*)d_in[8];
    const float* bt2 = (const float*)d_in[9];
    const float* W3  = (const float*)d_in[10];
    const float* b3  = (const float*)d_in[11];
    const float* g3  = (const float*)d_in[12];
    const float* bt3 = (const float*)d_in[13];
    const float* Wfc = (const float*)d_in[14];
    const float* bfc = (const float*)d_in[15];
    float* out = (float*)d_out;

    const int N = in_sizes[0] / 256;
    const int E = in_sizes[1] / 2;

    float *bufA, *bufB, *dis, *stats, *bnp;
    int *deg, *rowptr, *cursor, *bsum, *csr;
    cudaGetSymbolAddress((void**)&bufA,   g_bufA);
    cudaGetSymbolAddress((void**)&bufB,   g_bufB);
    cudaGetSymbolAddress((void**)&dis,    g_dis);
    cudaGetSymbolAddress((void**)&deg,    g_deg);
    cudaGetSymbolAddress((void**)&rowptr, g_rowptr);
    cudaGetSymbolAddress((void**)&cursor, g_cursor);
    cudaGetSymbolAddress((void**)&bsum,   g_bsum);
    cudaGetSymbolAddress((void**)&csr,    g_csr_src);
    cudaGetSymbolAddress((void**)&stats,  g_stats);
    cudaGetSymbolAddress((void**)&bnp,    g_bnp);

    // ---- degree / dis / CSR ----
    k_zero_int<<<cdiv(N, 256), 256>>>(deg, N);
    k_count_deg<<<cdiv(E, 256), 256>>>(ei, deg, E);
    k_dis<<<cdiv(N, 256), 256>>>(deg, dis, N);
    int nb = cdiv(N, 1024);
    k_scan_block<<<nb, 1024>>>(deg, rowptr, bsum, N);
    k_scan_bsum<<<1, 256>>>(bsum, nb);
    k_scan_add<<<cdiv(N, 256), 256>>>(rowptr, bsum, N);
    k_copy_int<<<cdiv(N, 256), 256>>>(cursor, rowptr, N);
    k_csr_scatter<<<cdiv(E, 256), 256>>>(ei, cursor, csr, E);

    // ================= Layer 1: 256 -> 128 =================
    {
        constexpr int F = 128;
        k_sgemm<128, 8><<<cdiv(N, 128), 256>>>(x, W1, bufA, N, 256, nullptr);
        k_gather<F><<<cdiv((long long)N * (F / 4), 256), 256>>>(rowptr, deg, csr, bufA, dis, b1, bufB, N);
        k_zero_f<<<1, 256>>>(stats, 2 * F);
        k_bn_stats<F><<<512, F>>>(bufB, stats, N);
        k_bn_finalize<<<1, F>>>(stats, g1, bt1, bnp, N, F);
    }
    // ================= Layer 2: 128 -> 64 =================
    {
        constexpr int F = 64;
        k_sgemm<64, 4><<<cdiv(N, 128), 256>>>(bufB, W2, bufA, N, 128, bnp);
        k_gather<F><<<cdiv((long long)N * (F / 4), 256), 256>>>(rowptr, deg, csr, bufA, dis, b2, bufB, N);
        k_zero_f<<<1, 256>>>(stats, 2 * F);
        k_bn_stats<F><<<512, F>>>(bufB, stats, N);
        k_bn_finalize<<<1, F>>>(stats, g2, bt2, bnp, N, F);
    }
    // ================= Layer 3: 64 -> 32 =================
    {
        constexpr int F = 32;
        k_sgemm<32, 2><<<cdiv(N, 128), 256>>>(bufB, W3, bufA, N, 64, bnp);
        k_gather<F><<<cdiv((long long)N * (F / 4), 256), 256>>>(rowptr, deg, csr, bufA, dis, b3, bufB, N);
        k_zero_f<<<1, 256>>>(stats, 2 * F);
        k_bn_stats<F><<<512, F>>>(bufB, stats, N);
        k_bn_finalize<<<1, F>>>(stats, g3, bt3, bnp, N, F);
    }
    // ================= Final FC: 32 -> 1 (fused BN+ReLU) =================
    k_final_fc<<<cdiv((long long)N * 32, 256), 256>>>(bufB, bnp, Wfc, bfc, out, N);
}

// round 5
// speedup vs baseline: 1.9011x; 1.1556x over previous
#include <cuda_runtime.h>
#include <cuda_fp16.h>
#include <cuda_bf16.h>
#include <cstdint>

#define MAXN 100000
#define MAXE 3200000
#define MAXF 128

// Scratch (device globals; no cudaMalloc allowed)
__device__ float  g_agg[(size_t)MAXN * MAXF];        // fp32 aggregation output
__device__ __half g_h16[(size_t)MAXN * MAXF];        // fp16 dis-prescaled features
__device__ float  g_dis[MAXN];
__device__ int    g_deg[MAXN];
__device__ int    g_rowptr[MAXN + 1];
__device__ int    g_cursor[MAXN + 1];
__device__ int    g_bsum[256];
__device__ int    g_csr_src[MAXE];
__device__ float  g_stats[2 * MAXF];
__device__ float  g_bnp[2 * MAXF];

// ---------------------------------------------------------------------------
// Degree / normalization / CSR build
// ---------------------------------------------------------------------------
__global__ void k_zero_int(int* p, int n) {
    int i = blockIdx.x * blockDim.x + threadIdx.x;
    if (i < n) p[i] = 0;
}
__global__ void k_zero_f(float* p, int n) {
    int i = blockIdx.x * blockDim.x + threadIdx.x;
    if (i < n) p[i] = 0.0f;
}
__global__ void k_count_deg(const int* __restrict__ ei, int* __restrict__ deg, int E) {
    int e = blockIdx.x * blockDim.x + threadIdx.x;
    if (e < E) atomicAdd(&deg[__ldg(ei + E + e)], 1);
}
__global__ void k_dis(const int* __restrict__ deg, float* __restrict__ dis, int N) {
    int i = blockIdx.x * blockDim.x + threadIdx.x;
    if (i < N) dis[i] = rsqrtf((float)deg[i] + 1.0f);
}

// exclusive scan of deg -> rowptr (3-kernel scheme)
__global__ void k_scan_block(const int* __restrict__ deg, int* __restrict__ exc,
                             int* __restrict__ bsum, int N)
{
    __shared__ int sh[1024];
    int i = blockIdx.x * 1024 + threadIdx.x;
    int v = (i < N) ? deg[i] : 0;
    sh[threadIdx.x] = v;
    __syncthreads();
#pragma unroll
    for (int o = 1; o < 1024; o <<= 1) {
        int t = (threadIdx.x >= o) ? sh[threadIdx.x - o] : 0;
        __syncthreads();
        sh[threadIdx.x] += t;
        __syncthreads();
    }
    if (i < N) exc[i] = sh[threadIdx.x] - v;
    if (threadIdx.x == 1023) bsum[blockIdx.x] = sh[1023];
}
__global__ void k_scan_bsum(int* bsum, int nb)
{
    __shared__ int sh[256];
    int t = threadIdx.x;
    int v = (t < nb) ? bsum[t] : 0;
    sh[t] = v;
    __syncthreads();
#pragma unroll
    for (int o = 1; o < 256; o <<= 1) {
        int u = (t >= o) ? sh[t - o] : 0;
        __syncthreads();
        sh[t] += u;
        __syncthreads();
    }
    if (t < nb) bsum[t] = sh[t] - v;   // exclusive
}
__global__ void k_scan_add(int* __restrict__ exc, const int* __restrict__ bsum, int N)
{
    int i = blockIdx.x * blockDim.x + threadIdx.x;
    if (i < N) exc[i] += bsum[i >> 10];
}
__global__ void k_copy_int(int* __restrict__ d, const int* __restrict__ s, int n)
{
    int i = blockIdx.x * blockDim.x + threadIdx.x;
    if (i < n) d[i] = s[i];
}
__global__ void k_csr_scatter(const int* __restrict__ ei, int* __restrict__ cursor,
                              int* __restrict__ csr_src, int E)
{
    int e = blockIdx.x * blockDim.x + threadIdx.x;
    if (e >= E) return;
    int src = __ldg(ei + e);
    int dst = __ldg(ei + E + e);
    int pos = atomicAdd(&cursor[dst], 1);
    csr_src[pos] = src;
}

// ---------------------------------------------------------------------------
// SGEMM: C16[M,BN] = half(dis[m] * (A[M,K] @ B[K,BN]))
// Optional fused BN+ReLU on A elements (prev layer's agg).
// BM=128, BK=32, 256 threads, 8xTN register tiles, float4 LDS.
// ---------------------------------------------------------------------------
template <int BN, int TN>
__global__ __launch_bounds__(256) void k_sgemm(
    const float* __restrict__ A, const float* __restrict__ B,
    __half* __restrict__ C16, const float* __restrict__ disv,
    int M, int K, const float* __restrict__ bnp)
{
    constexpr int BM = 128, BK = 32, TM = 8;
    __shared__ float As[BK][BM];
    __shared__ float Bs[BK][BN];
    const int tid  = threadIdx.x;
    const int tcol = tid & 15;
    const int trow = tid >> 4;
    const int m0   = blockIdx.x * BM;

    float acc[TM][TN];
#pragma unroll
    for (int i = 0; i < TM; i++)
#pragma unroll
        for (int j = 0; j < TN; j++) acc[i][j] = 0.0f;

    for (int k0 = 0; k0 < K; k0 += BK) {
#pragma unroll
        for (int i = 0; i < 4; i++) {
            int f    = tid + i * 256;
            int aRow = f >> 3;
            int aC4  = f & 7;
            float4 v = make_float4(0.f, 0.f, 0.f, 0.f);
            int gr = m0 + aRow;
            if (gr < M)
                v = *(const float4*)(A + (size_t)gr * K + k0 + aC4 * 4);
            if (bnp) {   // fused BN + ReLU
                int kidx = k0 + aC4 * 4;
                float4 sc = *(const float4*)(bnp + kidx);
                float4 sh = *(const float4*)(bnp + K + kidx);
                v.x = fmaxf(fmaf(v.x, sc.x, sh.x), 0.f);
                v.y = fmaxf(fmaf(v.y, sc.y, sh.y), 0.f);
                v.z = fmaxf(fmaf(v.z, sc.z, sh.z), 0.f);
                v.w = fmaxf(fmaf(v.w, sc.w, sh.w), 0.f);
            }
            As[aC4 * 4 + 0][aRow] = v.x;
            As[aC4 * 4 + 1][aRow] = v.y;
            As[aC4 * 4 + 2][aRow] = v.z;
            As[aC4 * 4 + 3][aRow] = v.w;
        }
        constexpr int BF4 = BK * BN / 4;
#pragma unroll
        for (int i = 0; i < BF4 / 256; i++) {
            int f    = tid + i * 256;
            int bRow = f / (BN / 4);
            int bC4  = f % (BN / 4);
            *(float4*)&Bs[bRow][bC4 * 4] =
                *(const float4*)(B + (size_t)(k0 + bRow) * BN + bC4 * 4);
        }
        __syncthreads();

#pragma unroll
        for (int kk = 0; kk < BK; kk++) {
            float ra[TM], rb[TN];
            *(float4*)&ra[0] = *(const float4*)&As[kk][trow * TM];
            *(float4*)&ra[4] = *(const float4*)&As[kk][trow * TM + 4];
            if (TN % 4 == 0) {
#pragma unroll
                for (int j = 0; j < TN; j += 4)
                    *(float4*)&rb[j] = *(const float4*)&Bs[kk][tcol * TN + j];
            } else {
#pragma unroll
                for (int j = 0; j < TN; j++) rb[j] = Bs[kk][tcol * TN + j];
            }
#pragma unroll
            for (int i = 0; i < TM; i++)
#pragma unroll
                for (int j = 0; j < TN; j++)
                    acc[i][j] = fmaf(ra[i], rb[j], acc[i][j]);
        }
        __syncthreads();
    }

    // Epilogue: scale row by dis[gm], convert to fp16, store
#pragma unroll
    for (int i = 0; i < TM; i++) {
        int gm = m0 + trow * TM + i;
        if (gm >= M) break;
        float d = __ldg(disv + gm);
        __half* dst = C16 + (size_t)gm * BN + tcol * TN;
        if (TN == 8) {
            __half2 h2[4];
#pragma unroll
            for (int j = 0; j < 4; j++)
                h2[j] = __floats2half2_rn(acc[i][2 * j] * d, acc[i][2 * j + 1] * d);
            *(uint4*)dst = *(uint4*)h2;
        } else if (TN == 4) {
            __half2 h2[2];
            h2[0] = __floats2half2_rn(acc[i][0] * d, acc[i][1] * d);
            h2[1] = __floats2half2_rn(acc[i][2] * d, acc[i][3] * d);
            *(uint2*)dst = *(uint2*)h2;
        } else {
            __half2 h2 = __floats2half2_rn(acc[i][0] * d, acc[i][1] * d);
            *(__half2*)dst = h2;
        }
    }
}

// ---------------------------------------------------------------------------
// CSR gather on fp16 prescaled rows:
//   agg[i] = dis[i] * ( sum_nbr h16[src] + h16[i] ) + bias
// G = F/8 lanes per node, uint4 (8 halfs) per lane, 2-edge unroll for MLP.
// ---------------------------------------------------------------------------
template <int F>
__global__ __launch_bounds__(256) void k_gather16(
    const int* __restrict__ rowptr, const int* __restrict__ deg,
    const int* __restrict__ csr_src, const __half* __restrict__ h16,
    const float* __restrict__ dis, const float* __restrict__ bias,
    float* __restrict__ agg, int N)
{
    constexpr int G = F / 8;
    int t    = blockIdx.x * 256 + threadIdx.x;
    int node = t / G;
    int j    = t - node * G;
    if (node >= N) return;

    int start = __ldg(rowptr + node);
    int cnt   = __ldg(deg + node);
    const __half* base = h16 + j * 8;

    float a[8];
#pragma unroll
    for (int q = 0; q < 8; q++) a[q] = 0.0f;

    auto addrow = [&](int s) {
        uint4 v = __ldg((const uint4*)(base + (size_t)s * F));
        const __half2* hv = (const __half2*)&v;
#pragma unroll
        for (int q = 0; q < 4; q++) {
            float2 f = __half22float2(hv[q]);
            a[2 * q]     += f.x;
            a[2 * q + 1] += f.y;
        }
    };

    int p = 0;
    for (; p + 2 <= cnt; p += 2) {
        int s0 = __ldg(csr_src + start + p);
        int s1 = __ldg(csr_src + start + p + 1);
        addrow(s0);
        addrow(s1);
    }
    if (p < cnt) addrow(__ldg(csr_src + start + p));
    addrow(node);   // self-loop (prescaled row already includes dis[node])

    float d = __ldg(dis + node);
    float4 b0 = __ldg((const float4*)(bias + j * 8));
    float4 b1 = __ldg((const float4*)(bias + j * 8) + 1);
    float4 r0, r1;
    r0.x = fmaf(d, a[0], b0.x); r0.y = fmaf(d, a[1], b0.y);
    r0.z = fmaf(d, a[2], b0.z); r0.w = fmaf(d, a[3], b0.w);
    r1.x = fmaf(d, a[4], b1.x); r1.y = fmaf(d, a[5], b1.y);
    r1.z = fmaf(d, a[6], b1.z); r1.w = fmaf(d, a[7], b1.w);
    float4* o = (float4*)(agg + (size_t)node * F + j * 8);
    o[0] = r0;
    o[1] = r1;
}

// ---------------------------------------------------------------------------
// BatchNorm stats / finalize
// ---------------------------------------------------------------------------
template <int F>
__global__ void k_bn_stats(const float* __restrict__ x, float* __restrict__ stats, int N)
{
    int f = threadIdx.x;
    float s = 0.f, sq = 0.f;
    for (int i = blockIdx.x; i < N; i += gridDim.x) {
        float v = x[(size_t)i * F + f];
        s += v;
        sq = fmaf(v, v, sq);
    }
    atomicAdd(&stats[f], s);
    atomicAdd(&stats[F + f], sq);
}

__global__ void k_bn_finalize(const float* __restrict__ stats,
                              const float* __restrict__ g, const float* __restrict__ bt,
                              float* __restrict__ bnp, int N, int F)
{
    int f = threadIdx.x;
    if (f >= F) return;
    float inv_n = 1.0f / (float)N;
    float mu  = stats[f] * inv_n;
    float var = fmaxf(stats[F + f] * inv_n - mu * mu, 0.0f);
    float sc = g[f] * rsqrtf(var + 1e-5f);
    bnp[f]     = sc;
    bnp[F + f] = bt[f] - mu * sc;
}

// ---------------------------------------------------------------------------
// Final FC with fused BN+ReLU: out[i] = relu(bn(agg3[i,:])) . Wfc + bfc
// ---------------------------------------------------------------------------
__global__ void k_final_fc(const float* __restrict__ h, const float* __restrict__ bnp,
                           const float* __restrict__ W, const float* __restrict__ b,
                           float* __restrict__ out, int N)
{
    int lane = threadIdx.x & 31;
    int node = (blockIdx.x * blockDim.x + threadIdx.x) >> 5;
    if (node >= N) return;
    float sc = __ldg(bnp + lane);
    float sh = __ldg(bnp + 32 + lane);
    float v = fmaxf(fmaf(h[(size_t)node * 32 + lane], sc, sh), 0.0f) * __ldg(W + lane);
#pragma unroll
    for (int o = 16; o; o >>= 1) v += __shfl_down_sync(0xFFFFFFFFu, v, o);
    if (lane == 0) out[node] = v + __ldg(b);
}

// ---------------------------------------------------------------------------
static inline int cdiv(long long a, long long b) { return (int)((a + b - 1) / b); }

extern "C" void kernel_launch(void* const* d_in, const int* in_sizes, int n_in,
                              void* d_out, int out_size)
{
    const float* x   = (const float*)d_in[0];
    const int*   ei  = (const int*)d_in[1];
    const float* W1  = (const float*)d_in[2];
    const float* b1  = (const float*)d_in[3];
    const float* g1  = (const float*)d_in[4];
    const float* bt1 = (const float*)d_in[5];
    const float* W2  = (const float*)d_in[6];
    const float* b2  = (const float*)d_in[7];
    const float* g2  = (const float*)d_in[8];
    const float* bt2 = (const float*)d_in[9];
    const float* W3  = (const float*)d_in[10];
    const float* b3  = (const float*)d_in[11];
    const float* g3  = (const float*)d_in[12];
    const float* bt3 = (const float*)d_in[13];
    const float* Wfc = (const float*)d_in[14];
    const float* bfc = (const float*)d_in[15];
    float* out = (float*)d_out;

    const int N = in_sizes[0] / 256;
    const int E = in_sizes[1] / 2;

    float *agg, *dis, *stats, *bnp;
    __half* h16;
    int *deg, *rowptr, *cursor, *bsum, *csr;
    cudaGetSymbolAddress((void**)&agg,    g_agg);
    cudaGetSymbolAddress((void**)&h16,    g_h16);
    cudaGetSymbolAddress((void**)&dis,    g_dis);
    cudaGetSymbolAddress((void**)&deg,    g_deg);
    cudaGetSymbolAddress((void**)&rowptr, g_rowptr);
    cudaGetSymbolAddress((void**)&cursor, g_cursor);
    cudaGetSymbolAddress((void**)&bsum,   g_bsum);
    cudaGetSymbolAddress((void**)&csr,    g_csr_src);
    cudaGetSymbolAddress((void**)&stats,  g_stats);
    cudaGetSymbolAddress((void**)&bnp,    g_bnp);

    // ---- degree / dis / CSR ----
    k_zero_int<<<cdiv(N, 256), 256>>>(deg, N);
    k_count_deg<<<cdiv(E, 256), 256>>>(ei, deg, E);
    k_dis<<<cdiv(N, 256), 256>>>(deg, dis, N);
    int nb = cdiv(N, 1024);
    k_scan_block<<<nb, 1024>>>(deg, rowptr, bsum, N);
    k_scan_bsum<<<1, 256>>>(bsum, nb);
    k_scan_add<<<cdiv(N, 256), 256>>>(rowptr, bsum, N);
    k_copy_int<<<cdiv(N, 256), 256>>>(cursor, rowptr, N);
    k_csr_scatter<<<cdiv(E, 256), 256>>>(ei, cursor, csr, E);

    // ================= Layer 1: 256 -> 128 =================
    {
        constexpr int F = 128;
        k_sgemm<128, 8><<<cdiv(N, 128), 256>>>(x, W1, h16, dis, N, 256, nullptr);
        k_gather16<F><<<cdiv((long long)N * (F / 8), 256), 256>>>(rowptr, deg, csr, h16, dis, b1, agg, N);
        k_zero_f<<<1, 256>>>(stats, 2 * F);
        k_bn_stats<F><<<512, F>>>(agg, stats, N);
        k_bn_finalize<<<1, F>>>(stats, g1, bt1, bnp, N, F);
    }
    // ================= Layer 2: 128 -> 64 =================
    {
        constexpr int F = 64;
        k_sgemm<64, 4><<<cdiv(N, 128), 256>>>(agg, W2, h16, dis, N, 128, bnp);
        k_gather16<F><<<cdiv((long long)N * (F / 8), 256), 256>>>(rowptr, deg, csr, h16, dis, b2, agg, N);
        k_zero_f<<<1, 256>>>(stats, 2 * F);
        k_bn_stats<F><<<512, F>>>(agg, stats, N);
        k_bn_finalize<<<1, F>>>(stats, g2, bt2, bnp, N, F);
    }
    // ================= Layer 3: 64 -> 32 =================
    {
        constexpr int F = 32;
        k_sgemm<32, 2><<<cdiv(N, 128), 256>>>(agg, W3, h16, dis, N, 64, bnp);
        k_gather16<F><<<cdiv((long long)N * (F / 8), 256), 256>>>(rowptr, deg, csr, h16, dis, b3, agg, N);
        k_zero_f<<<1, 256>>>(stats, 2 * F);
        k_bn_stats<F><<<512, F>>>(agg, stats, N);
        k_bn_finalize<<<1, F>>>(stats, g3, bt3, bnp, N, F);
    }
    // ================= Final FC: 32 -> 1 (fused BN+ReLU) =================
    k_final_fc<<<cdiv((long long)N * 32, 256), 256>>>(agg, bnp, Wfc, bfc, out, N);
}

// round 6
// speedup vs baseline: 2.2167x; 1.1660x over previous
#include <cuda_runtime.h>
#include <cuda_fp16.h>
#include <cuda_bf16.h>
#include <cstdint>

#define MAXN 100000
#define MAXE 3200000
#define MAXF 128

// Scratch (device globals; no cudaMalloc allowed)
__device__ float  g_agg[(size_t)MAXN * MAXF];        // fp32 aggregation output
__device__ __half g_h16[(size_t)MAXN * MAXF];        // fp16 dis-prescaled features
__device__ float  g_dis[MAXN];
__device__ int    g_deg[MAXN];
__device__ int    g_rowptr[MAXN + 1];
__device__ int    g_cursor[MAXN + 1];
__device__ int    g_bsum[256];
__device__ int    g_csr_src[MAXE];
__device__ float  g_stats[2 * MAXF];
__device__ float  g_bnp[2 * MAXF];
__device__ __half g_whi[256 * 128];                  // split weights, transposed [N][K]
__device__ __half g_wlo[256 * 128];

// ---------------------------------------------------------------------------
// Degree / normalization / CSR build
// ---------------------------------------------------------------------------
__global__ void k_zero_int(int* p, int n) {
    int i = blockIdx.x * blockDim.x + threadIdx.x;
    if (i < n) p[i] = 0;
}
__global__ void k_zero_f(float* p, int n) {
    int i = blockIdx.x * blockDim.x + threadIdx.x;
    if (i < n) p[i] = 0.0f;
}
__global__ void k_count_deg(const int* __restrict__ ei, int* __restrict__ deg, int E) {
    int e = blockIdx.x * blockDim.x + threadIdx.x;
    if (e < E) atomicAdd(&deg[__ldg(ei + E + e)], 1);
}
__global__ void k_dis(const int* __restrict__ deg, float* __restrict__ dis, int N) {
    int i = blockIdx.x * blockDim.x + threadIdx.x;
    if (i < N) dis[i] = rsqrtf((float)deg[i] + 1.0f);
}

// exclusive scan of deg -> rowptr (3-kernel scheme)
__global__ void k_scan_block(const int* __restrict__ deg, int* __restrict__ exc,
                             int* __restrict__ bsum, int N)
{
    __shared__ int sh[1024];
    int i = blockIdx.x * 1024 + threadIdx.x;
    int v = (i < N) ? deg[i] : 0;
    sh[threadIdx.x] = v;
    __syncthreads();
#pragma unroll
    for (int o = 1; o < 1024; o <<= 1) {
        int t = (threadIdx.x >= o) ? sh[threadIdx.x - o] : 0;
        __syncthreads();
        sh[threadIdx.x] += t;
        __syncthreads();
    }
    if (i < N) exc[i] = sh[threadIdx.x] - v;
    if (threadIdx.x == 1023) bsum[blockIdx.x] = sh[1023];
}
__global__ void k_scan_bsum(int* bsum, int nb)
{
    __shared__ int sh[256];
    int t = threadIdx.x;
    int v = (t < nb) ? bsum[t] : 0;
    sh[t] = v;
    __syncthreads();
#pragma unroll
    for (int o = 1; o < 256; o <<= 1) {
        int u = (t >= o) ? sh[t - o] : 0;
        __syncthreads();
        sh[t] += u;
        __syncthreads();
    }
    if (t < nb) bsum[t] = sh[t] - v;   // exclusive
}
__global__ void k_scan_add2(int* __restrict__ rowptr, int* __restrict__ cursor,
                            const int* __restrict__ bsum, int N)
{
    int i = blockIdx.x * blockDim.x + threadIdx.x;
    if (i < N) {
        int v = rowptr[i] + bsum[i >> 10];
        rowptr[i] = v;
        cursor[i] = v;
    }
}
__global__ void k_csr_scatter(const int* __restrict__ ei, int* __restrict__ cursor,
                              int* __restrict__ csr_src, int E)
{
    int e = blockIdx.x * blockDim.x + threadIdx.x;
    if (e >= E) return;
    int src = __ldg(ei + e);
    int dst = __ldg(ei + E + e);
    int pos = atomicAdd(&cursor[dst], 1);
    csr_src[pos] = src;
}

// ---------------------------------------------------------------------------
// Weight split: W[K][N] fp32 -> Whi/Wlo [N][K] fp16 (hi + residual)
// ---------------------------------------------------------------------------
__global__ void k_splitW(const float* __restrict__ W, __half* __restrict__ Wh,
                         __half* __restrict__ Wl, int K, int N)
{
    int i = blockIdx.x * blockDim.x + threadIdx.x;
    if (i >= N * K) return;
    int n = i / K, k = i - n * K;
    float v = __ldg(W + (size_t)k * N + n);
    __half h = __float2half_rn(v);
    Wh[i] = h;
    Wl[i] = __float2half_rn(v - __half2float(h));
}

// ---------------------------------------------------------------------------
// Split-fp16 tensor-core GEMM:
//   C16[M,BN] = half( dis[m] * (A[M,K] @ W[K,BN]) )
// A fp32 (optionally BN+ReLU'd in the loader), W pre-split as Whi/Wlo [BN][K].
// Computes AhiWhi + AhiWlo + AloWhi  (fp32-accurate to ~2^-22).
// BM=128, BK=32, 256 threads (8 warps as 2x4), warp tile 64 x (BN/4).
// ---------------------------------------------------------------------------
__device__ __forceinline__ void mma16816(float* c, const uint32_t* a, const uint32_t* b)
{
    asm volatile(
        "mma.sync.aligned.m16n8k16.row.col.f32.f16.f16.f32 "
        "{%0,%1,%2,%3}, {%4,%5,%6,%7}, {%8,%9}, {%0,%1,%2,%3};"
        : "+f"(c[0]), "+f"(c[1]), "+f"(c[2]), "+f"(c[3])
        : "r"(a[0]), "r"(a[1]), "r"(a[2]), "r"(a[3]), "r"(b[0]), "r"(b[1]));
}

template <int BN>
__global__ __launch_bounds__(256) void k_mma_gemm(
    const float* __restrict__ A, const __half* __restrict__ Wh,
    const __half* __restrict__ Wl, __half* __restrict__ C16,
    const float* __restrict__ disv, int M, int K, const float* __restrict__ bnp)
{
    constexpr int BM = 128, BK = 32;
    constexpr int LDA = BK + 8;           // halfs; 80B row stride
    constexpr int MT = 4;                 // 4 m16 tiles per warp (wm=64)
    constexpr int NT = BN / 32;           // n8 tiles per warp (wn=BN/4)
    constexpr int WNW = BN / 4;

    __shared__ __align__(16) __half Ah[BM][LDA];
    __shared__ __align__(16) __half Al[BM][LDA];
    __shared__ __align__(16) __half Bh[BN][LDA];
    __shared__ __align__(16) __half Bl[BN][LDA];

    const int tid  = threadIdx.x;
    const int warp = tid >> 5;
    const int lane = tid & 31;
    const int g    = lane >> 2;
    const int t4   = lane & 3;
    const int wmi  = warp & 1;
    const int wni  = warp >> 1;
    const int m0   = blockIdx.x * BM;

    float acc[MT][NT][4];
#pragma unroll
    for (int mt = 0; mt < MT; mt++)
#pragma unroll
        for (int nt = 0; nt < NT; nt++)
#pragma unroll
            for (int q = 0; q < 4; q++) acc[mt][nt][q] = 0.0f;

    for (int k0 = 0; k0 < K; k0 += BK) {
        // ---- stage A tile (fp32 -> hi/lo fp16), fused BN+ReLU ----
#pragma unroll
        for (int i = 0; i < 4; i++) {
            int idx = tid + i * 256;        // 0..1023 float4 slots
            int row = idx >> 3;
            int c4  = idx & 7;
            float4 v = make_float4(0.f, 0.f, 0.f, 0.f);
            int gr = m0 + row;
            if (gr < M)
                v = *(const float4*)(A + (size_t)gr * K + k0 + c4 * 4);
            if (bnp) {
                int kidx = k0 + c4 * 4;
                float4 sc = *(const float4*)(bnp + kidx);
                float4 sh = *(const float4*)(bnp + K + kidx);
                v.x = fmaxf(fmaf(v.x, sc.x, sh.x), 0.f);
                v.y = fmaxf(fmaf(v.y, sc.y, sh.y), 0.f);
                v.z = fmaxf(fmaf(v.z, sc.z, sh.z), 0.f);
                v.w = fmaxf(fmaf(v.w, sc.w, sh.w), 0.f);
            }
            float f[4] = {v.x, v.y, v.z, v.w};
            __half h[4], l[4];
#pragma unroll
            for (int q = 0; q < 4; q++) {
                h[q] = __float2half_rn(f[q]);
                l[q] = __float2half_rn(f[q] - __half2float(h[q]));
            }
            uint2 uh, ul;
            ((__half2*)&uh)[0] = __halves2half2(h[0], h[1]);
            ((__half2*)&uh)[1] = __halves2half2(h[2], h[3]);
            ((__half2*)&ul)[0] = __halves2half2(l[0], l[1]);
            ((__half2*)&ul)[1] = __halves2half2(l[2], l[3]);
            *(uint2*)&Ah[row][c4 * 4] = uh;
            *(uint2*)&Al[row][c4 * 4] = ul;
        }
        // ---- stage B tile (already split & transposed: [BN][K]) ----
#pragma unroll
        for (int i = 0; i < (BN * 4 + 255) / 256; i++) {
            int idx = tid + i * 256;
            if (idx < BN * 4) {
                int n  = idx >> 2;
                int c8 = idx & 3;
                *(uint4*)&Bh[n][c8 * 8] = *(const uint4*)(Wh + (size_t)n * K + k0 + c8 * 8);
                *(uint4*)&Bl[n][c8 * 8] = *(const uint4*)(Wl + (size_t)n * K + k0 + c8 * 8);
            }
        }
        __syncthreads();

#pragma unroll
        for (int kk = 0; kk < BK; kk += 16) {
            uint32_t ah[MT][4], al[MT][4], bh[NT][2], bl[NT][2];
#pragma unroll
            for (int mt = 0; mt < MT; mt++) {
                int r = wmi * 64 + mt * 16 + g;
                ah[mt][0] = *(const uint32_t*)&Ah[r][kk + t4 * 2];
                ah[mt][1] = *(const uint32_t*)&Ah[r + 8][kk + t4 * 2];
                ah[mt][2] = *(const uint32_t*)&Ah[r][kk + t4 * 2 + 8];
                ah[mt][3] = *(const uint32_t*)&Ah[r + 8][kk + t4 * 2 + 8];
                al[mt][0] = *(const uint32_t*)&Al[r][kk + t4 * 2];
                al[mt][1] = *(const uint32_t*)&Al[r + 8][kk + t4 * 2];
                al[mt][2] = *(const uint32_t*)&Al[r][kk + t4 * 2 + 8];
                al[mt][3] = *(const uint32_t*)&Al[r + 8][kk + t4 * 2 + 8];
            }
#pragma unroll
            for (int nt = 0; nt < NT; nt++) {
                int n = wni * WNW + nt * 8 + g;
                bh[nt][0] = *(const uint32_t*)&Bh[n][kk + t4 * 2];
                bh[nt][1] = *(const uint32_t*)&Bh[n][kk + t4 * 2 + 8];
                bl[nt][0] = *(const uint32_t*)&Bl[n][kk + t4 * 2];
                bl[nt][1] = *(const uint32_t*)&Bl[n][kk + t4 * 2 + 8];
            }
#pragma unroll
            for (int mt = 0; mt < MT; mt++)
#pragma unroll
                for (int nt = 0; nt < NT; nt++) {
                    mma16816(acc[mt][nt], ah[mt], bh[nt]);
                    mma16816(acc[mt][nt], ah[mt], bl[nt]);
                    mma16816(acc[mt][nt], al[mt], bh[nt]);
                }
        }
        __syncthreads();
    }

    // ---- epilogue: scale by dis, convert to fp16, store ----
#pragma unroll
    for (int mt = 0; mt < MT; mt++) {
#pragma unroll
        for (int nt = 0; nt < NT; nt++) {
            int r0 = m0 + wmi * 64 + mt * 16 + g;
            int r1 = r0 + 8;
            int c  = wni * WNW + nt * 8 + t4 * 2;
            if (r0 < M) {
                float d = __ldg(disv + r0);
                *(__half2*)&C16[(size_t)r0 * BN + c] =
                    __floats2half2_rn(acc[mt][nt][0] * d, acc[mt][nt][1] * d);
            }
            if (r1 < M) {
                float d = __ldg(disv + r1);
                *(__half2*)&C16[(size_t)r1 * BN + c] =
                    __floats2half2_rn(acc[mt][nt][2] * d, acc[mt][nt][3] * d);
            }
        }
    }
}

// ---------------------------------------------------------------------------
// CSR gather on fp16 prescaled rows:
//   agg[i] = dis[i] * ( sum_nbr h16[src] + h16[i] ) + bias
// ---------------------------------------------------------------------------
template <int F>
__global__ __launch_bounds__(256) void k_gather16(
    const int* __restrict__ rowptr, const int* __restrict__ deg,
    const int* __restrict__ csr_src, const __half* __restrict__ h16,
    const float* __restrict__ dis, const float* __restrict__ bias,
    float* __restrict__ agg, int N)
{
    constexpr int G = F / 8;
    int t    = blockIdx.x * 256 + threadIdx.x;
    int node = t / G;
    int j    = t - node * G;
    if (node >= N) return;

    int start = __ldg(rowptr + node);
    int cnt   = __ldg(deg + node);
    const __half* base = h16 + j * 8;

    float a[8];
#pragma unroll
    for (int q = 0; q < 8; q++) a[q] = 0.0f;

    auto addrow = [&](int s) {
        uint4 v = __ldg((const uint4*)(base + (size_t)s * F));
        const __half2* hv = (const __half2*)&v;
#pragma unroll
        for (int q = 0; q < 4; q++) {
            float2 f = __half22float2(hv[q]);
            a[2 * q]     += f.x;
            a[2 * q + 1] += f.y;
        }
    };

    int p = 0;
    for (; p + 2 <= cnt; p += 2) {
        int s0 = __ldg(csr_src + start + p);
        int s1 = __ldg(csr_src + start + p + 1);
        addrow(s0);
        addrow(s1);
    }
    if (p < cnt) addrow(__ldg(csr_src + start + p));
    addrow(node);   // self-loop (row already prescaled by dis[node])

    float d = __ldg(dis + node);
    float4 b0 = __ldg((const float4*)(bias + j * 8));
    float4 b1 = __ldg((const float4*)(bias + j * 8) + 1);
    float4 r0, r1;
    r0.x = fmaf(d, a[0], b0.x); r0.y = fmaf(d, a[1], b0.y);
    r0.z = fmaf(d, a[2], b0.z); r0.w = fmaf(d, a[3], b0.w);
    r1.x = fmaf(d, a[4], b1.x); r1.y = fmaf(d, a[5], b1.y);
    r1.z = fmaf(d, a[6], b1.z); r1.w = fmaf(d, a[7], b1.w);
    float4* o = (float4*)(agg + (size_t)node * F + j * 8);
    o[0] = r0;
    o[1] = r1;
}

// ---------------------------------------------------------------------------
// BatchNorm stats / finalize
// ---------------------------------------------------------------------------
template <int F>
__global__ void k_bn_stats(const float* __restrict__ x, float* __restrict__ stats, int N)
{
    int f = threadIdx.x;
    float s = 0.f, sq = 0.f;
    for (int i = blockIdx.x; i < N; i += gridDim.x) {
        float v = x[(size_t)i * F + f];
        s += v;
        sq = fmaf(v, v, sq);
    }
    atomicAdd(&stats[f], s);
    atomicAdd(&stats[F + f], sq);
}

__global__ void k_bn_finalize(const float* __restrict__ stats,
                              const float* __restrict__ g, const float* __restrict__ bt,
                              float* __restrict__ bnp, int N, int F)
{
    int f = threadIdx.x;
    if (f >= F) return;
    float inv_n = 1.0f / (float)N;
    float mu  = stats[f] * inv_n;
    float var = fmaxf(stats[F + f] * inv_n - mu * mu, 0.0f);
    float sc = g[f] * rsqrtf(var + 1e-5f);
    bnp[f]     = sc;
    bnp[F + f] = bt[f] - mu * sc;
}

// ---------------------------------------------------------------------------
// Final FC with fused BN+ReLU
// ---------------------------------------------------------------------------
__global__ void k_final_fc(const float* __restrict__ h, const float* __restrict__ bnp,
                           const float* __restrict__ W, const float* __restrict__ b,
                           float* __restrict__ out, int N)
{
    int lane = threadIdx.x & 31;
    int node = (blockIdx.x * blockDim.x + threadIdx.x) >> 5;
    if (node >= N) return;
    float sc = __ldg(bnp + lane);
    float sh = __ldg(bnp + 32 + lane);
    float v = fmaxf(fmaf(h[(size_t)node * 32 + lane], sc, sh), 0.0f) * __ldg(W + lane);
#pragma unroll
    for (int o = 16; o; o >>= 1) v += __shfl_down_sync(0xFFFFFFFFu, v, o);
    if (lane == 0) out[node] = v + __ldg(b);
}

// ---------------------------------------------------------------------------
static inline int cdiv(long long a, long long b) { return (int)((a + b - 1) / b); }

extern "C" void kernel_launch(void* const* d_in, const int* in_sizes, int n_in,
                              void* d_out, int out_size)
{
    const float* x   = (const float*)d_in[0];
    const int*   ei  = (const int*)d_in[1];
    const float* W1  = (const float*)d_in[2];
    const float* b1  = (const float*)d_in[3];
    const float* g1  = (const float*)d_in[4];
    const float* bt1 = (const float*)d_in[5];
    const float* W2  = (const float*)d_in[6];
    const float* b2  = (const float*)d_in[7];
    const float* g2  = (const float*)d_in[8];
    const float* bt2 = (const float*)d_in[9];
    const float* W3  = (const float*)d_in[10];
    const float* b3  = (const float*)d_in[11];
    const float* g3  = (const float*)d_in[12];
    const float* bt3 = (const float*)d_in[13];
    const float* Wfc = (const float*)d_in[14];
    const float* bfc = (const float*)d_in[15];
    float* out = (float*)d_out;

    const int N = in_sizes[0] / 256;
    const int E = in_sizes[1] / 2;

    float *agg, *dis, *stats, *bnp;
    __half *h16, *whi, *wlo;
    int *deg, *rowptr, *cursor, *bsum, *csr;
    cudaGetSymbolAddress((void**)&agg,    g_agg);
    cudaGetSymbolAddress((void**)&h16,    g_h16);
    cudaGetSymbolAddress((void**)&dis,    g_dis);
    cudaGetSymbolAddress((void**)&deg,    g_deg);
    cudaGetSymbolAddress((void**)&rowptr, g_rowptr);
    cudaGetSymbolAddress((void**)&cursor, g_cursor);
    cudaGetSymbolAddress((void**)&bsum,   g_bsum);
    cudaGetSymbolAddress((void**)&csr,    g_csr_src);
    cudaGetSymbolAddress((void**)&stats,  g_stats);
    cudaGetSymbolAddress((void**)&bnp,    g_bnp);
    cudaGetSymbolAddress((void**)&whi,    g_whi);
    cudaGetSymbolAddress((void**)&wlo,    g_wlo);

    // ---- degree / dis / CSR ----
    k_zero_int<<<cdiv(N, 256), 256>>>(deg, N);
    k_count_deg<<<cdiv(E, 256), 256>>>(ei, deg, E);
    k_dis<<<cdiv(N, 256), 256>>>(deg, dis, N);
    int nb = cdiv(N, 1024);
    k_scan_block<<<nb, 1024>>>(deg, rowptr, bsum, N);
    k_scan_bsum<<<1, 256>>>(bsum, nb);
    k_scan_add2<<<cdiv(N, 256), 256>>>(rowptr, cursor, bsum, N);
    k_csr_scatter<<<cdiv(E, 256), 256>>>(ei, cursor, csr, E);

    // ================= Layer 1: 256 -> 128 =================
    {
        constexpr int F = 128;
        k_splitW<<<cdiv(256 * 128, 256), 256>>>(W1, whi, wlo, 256, F);
        k_mma_gemm<128><<<cdiv(N, 128), 256>>>(x, whi, wlo, h16, dis, N, 256, nullptr);
        k_gather16<F><<<cdiv((long long)N * (F / 8), 256), 256>>>(rowptr, deg, csr, h16, dis, b1, agg, N);
        k_zero_f<<<1, 256>>>(stats, 2 * F);
        k_bn_stats<F><<<512, F>>>(agg, stats, N);
        k_bn_finalize<<<1, F>>>(stats, g1, bt1, bnp, N, F);
    }
    // ================= Layer 2: 128 -> 64 =================
    {
        constexpr int F = 64;
        k_splitW<<<cdiv(128 * 64, 256), 256>>>(W2, whi, wlo, 128, F);
        k_mma_gemm<64><<<cdiv(N, 128), 256>>>(agg, whi, wlo, h16, dis, N, 128, bnp);
        k_gather16<F><<<cdiv((long long)N * (F / 8), 256), 256>>>(rowptr, deg, csr, h16, dis, b2, agg, N);
        k_zero_f<<<1, 256>>>(stats, 2 * F);
        k_bn_stats<F><<<512, F>>>(agg, stats, N);
        k_bn_finalize<<<1, F>>>(stats, g2, bt2, bnp, N, F);
    }
    // ================= Layer 3: 64 -> 32 =================
    {
        constexpr int F = 32;
        k_splitW<<<cdiv(64 * 32, 256), 256>>>(W3, whi, wlo, 64, F);
        k_mma_gemm<32><<<cdiv(N, 128), 256>>>(agg, whi, wlo, h16, dis, N, 64, bnp);
        k_gather16<F><<<cdiv((long long)N * (F / 8), 256), 256>>>(rowptr, deg, csr, h16, dis, b3, agg, N);
        k_zero_f<<<1, 256>>>(stats, 2 * F);
        k_bn_stats<F><<<512, F>>>(agg, stats, N);
        k_bn_finalize<<<1, F>>>(stats, g3, bt3, bnp, N, F);
    }
    // ================= Final FC: 32 -> 1 (fused BN+ReLU) =================
    k_final_fc<<<cdiv((long long)N * 32, 256), 256>>>(agg, bnp, Wfc, bfc, out, N);
}

// round 7
// speedup vs baseline: 2.6587x; 1.1994x over previous
#include <cuda_runtime.h>
#include <cuda_fp16.h>
#include <cuda_bf16.h>
#include <cstdint>

#define MAXN 100000
#define MAXE 3200000
#define MAXF 128

// Scratch (device globals; no cudaMalloc allowed)
__device__ float  g_agg[(size_t)MAXN * MAXF];        // fp32 aggregation output
__device__ __half g_h16[(size_t)MAXN * MAXF];        // fp16 dis-prescaled features
__device__ float  g_dis[MAXN];
__device__ int    g_deg[MAXN];
__device__ int    g_rowptr[MAXN + 1];
__device__ int    g_cursor[MAXN + 1];
__device__ int    g_bsum[256];
__device__ int    g_csr_src[MAXE];
__device__ float  g_stats[2 * MAXF];
__device__ float  g_bnp[2 * MAXF];
__device__ __half g_whi[256 * 128 + 128 * 64 + 64 * 32];  // split weights, transposed [N][K]
__device__ __half g_wlo[256 * 128 + 128 * 64 + 64 * 32];

#define W2_OFF (256 * 128)
#define W3_OFF (256 * 128 + 128 * 64)

// ---------------------------------------------------------------------------
// Degree / normalization / CSR build
// ---------------------------------------------------------------------------
__global__ void k_zero_int(int* p, int n) {
    int i = blockIdx.x * blockDim.x + threadIdx.x;
    if (i < n) p[i] = 0;
}
__global__ void k_count_deg(const int* __restrict__ ei, int* __restrict__ deg, int E) {
    int e = blockIdx.x * blockDim.x + threadIdx.x;
    if (e < E) atomicAdd(&deg[__ldg(ei + E + e)], 1);
}
__global__ void k_dis(const int* __restrict__ deg, float* __restrict__ dis, int N) {
    int i = blockIdx.x * blockDim.x + threadIdx.x;
    if (i < N) dis[i] = rsqrtf((float)deg[i] + 1.0f);
}

// exclusive scan of deg -> rowptr (3-kernel scheme)
__global__ void k_scan_block(const int* __restrict__ deg, int* __restrict__ exc,
                             int* __restrict__ bsum, int N)
{
    __shared__ int sh[1024];
    int i = blockIdx.x * 1024 + threadIdx.x;
    int v = (i < N) ? deg[i] : 0;
    sh[threadIdx.x] = v;
    __syncthreads();
#pragma unroll
    for (int o = 1; o < 1024; o <<= 1) {
        int t = (threadIdx.x >= o) ? sh[threadIdx.x - o] : 0;
        __syncthreads();
        sh[threadIdx.x] += t;
        __syncthreads();
    }
    if (i < N) exc[i] = sh[threadIdx.x] - v;
    if (threadIdx.x == 1023) bsum[blockIdx.x] = sh[1023];
}
__global__ void k_scan_bsum(int* bsum, int nb)
{
    __shared__ int sh[256];
    int t = threadIdx.x;
    int v = (t < nb) ? bsum[t] : 0;
    sh[t] = v;
    __syncthreads();
#pragma unroll
    for (int o = 1; o < 256; o <<= 1) {
        int u = (t >= o) ? sh[t - o] : 0;
        __syncthreads();
        sh[t] += u;
        __syncthreads();
    }
    if (t < nb) bsum[t] = sh[t] - v;   // exclusive
}
// adds block offsets, mirrors rowptr->cursor, and zeroes the BN stats buffer
__global__ void k_scan_add2(int* __restrict__ rowptr, int* __restrict__ cursor,
                            const int* __restrict__ bsum, float* __restrict__ stats, int N)
{
    int i = blockIdx.x * blockDim.x + threadIdx.x;
    if (i < N) {
        int v = rowptr[i] + bsum[i >> 10];
        rowptr[i] = v;
        cursor[i] = v;
    }
    if (blockIdx.x == 0 && threadIdx.x < 2 * MAXF) stats[threadIdx.x] = 0.0f;
}
__global__ void k_csr_scatter(const int* __restrict__ ei, int* __restrict__ cursor,
                              int* __restrict__ csr_src, int E)
{
    int e = blockIdx.x * blockDim.x + threadIdx.x;
    if (e >= E) return;
    int src = __ldg(ei + e);
    int dst = __ldg(ei + E + e);
    int pos = atomicAdd(&cursor[dst], 1);
    csr_src[pos] = src;
}

// ---------------------------------------------------------------------------
// Weight split (all 3 layers in one launch):
//   W[K][N] fp32 -> Whi/Wlo [N][K] fp16 (hi + residual), at per-layer offsets
// ---------------------------------------------------------------------------
__global__ void k_splitW_all(const float* __restrict__ W1, const float* __restrict__ W2,
                             const float* __restrict__ W3,
                             __half* __restrict__ Wh, __half* __restrict__ Wl)
{
    int i = blockIdx.x * blockDim.x + threadIdx.x;
    const float* W;
    int K, Nn, off, li;
    if (i < W2_OFF)            { W = W1; K = 256; Nn = 128; off = 0;      li = i; }
    else if (i < W3_OFF)       { W = W2; K = 128; Nn = 64;  off = W2_OFF; li = i - W2_OFF; }
    else if (i < W3_OFF + 64 * 32) { W = W3; K = 64; Nn = 32; off = W3_OFF; li = i - W3_OFF; }
    else return;
    int n = li / K, k = li - n * K;
    float v = __ldg(W + (size_t)k * Nn + n);
    __half h = __float2half_rn(v);
    Wh[off + li] = h;
    Wl[off + li] = __float2half_rn(v - __half2float(h));
}

// ---------------------------------------------------------------------------
// Split-fp16 tensor-core GEMM:
//   C16[M,BN] = half( dis[m] * (A[M,K] @ W[K,BN]) )
// A fp32 (optionally BN+ReLU'd in the loader), W pre-split as Whi/Wlo [BN][K].
// Computes AhiWhi + AhiWlo + AloWhi  (fp32-accurate to ~2^-22).
// BM=128, BK=32, 256 threads (8 warps as 2x4), warp tile 64 x (BN/4).
// ---------------------------------------------------------------------------
__device__ __forceinline__ void mma16816(float* c, const uint32_t* a, const uint32_t* b)
{
    asm volatile(
        "mma.sync.aligned.m16n8k16.row.col.f32.f16.f16.f32 "
        "{%0,%1,%2,%3}, {%4,%5,%6,%7}, {%8,%9}, {%0,%1,%2,%3};"
        : "+f"(c[0]), "+f"(c[1]), "+f"(c[2]), "+f"(c[3])
        : "r"(a[0]), "r"(a[1]), "r"(a[2]), "r"(a[3]), "r"(b[0]), "r"(b[1]));
}

template <int BN>
__global__ __launch_bounds__(256) void k_mma_gemm(
    const float* __restrict__ A, const __half* __restrict__ Wh,
    const __half* __restrict__ Wl, __half* __restrict__ C16,
    const float* __restrict__ disv, int M, int K, const float* __restrict__ bnp)
{
    constexpr int BM = 128, BK = 32;
    constexpr int LDA = BK + 8;           // halfs; 80B row stride
    constexpr int MT = 4;                 // 4 m16 tiles per warp (wm=64)
    constexpr int NT = BN / 32;           // n8 tiles per warp (wn=BN/4)
    constexpr int WNW = BN / 4;

    __shared__ __align__(16) __half Ah[BM][LDA];
    __shared__ __align__(16) __half Al[BM][LDA];
    __shared__ __align__(16) __half Bh[BN][LDA];
    __shared__ __align__(16) __half Bl[BN][LDA];

    const int tid  = threadIdx.x;
    const int warp = tid >> 5;
    const int lane = tid & 31;
    const int g    = lane >> 2;
    const int t4   = lane & 3;
    const int wmi  = warp & 1;
    const int wni  = warp >> 1;
    const int m0   = blockIdx.x * BM;

    float acc[MT][NT][4];
#pragma unroll
    for (int mt = 0; mt < MT; mt++)
#pragma unroll
        for (int nt = 0; nt < NT; nt++)
#pragma unroll
            for (int q = 0; q < 4; q++) acc[mt][nt][q] = 0.0f;

    for (int k0 = 0; k0 < K; k0 += BK) {
        // ---- stage A tile (fp32 -> hi/lo fp16), fused BN+ReLU ----
#pragma unroll
        for (int i = 0; i < 4; i++) {
            int idx = tid + i * 256;        // 0..1023 float4 slots
            int row = idx >> 3;
            int c4  = idx & 7;
            float4 v = make_float4(0.f, 0.f, 0.f, 0.f);
            int gr = m0 + row;
            if (gr < M)
                v = *(const float4*)(A + (size_t)gr * K + k0 + c4 * 4);
            if (bnp) {
                int kidx = k0 + c4 * 4;
                float4 sc = *(const float4*)(bnp + kidx);
                float4 sh = *(const float4*)(bnp + K + kidx);
                v.x = fmaxf(fmaf(v.x, sc.x, sh.x), 0.f);
                v.y = fmaxf(fmaf(v.y, sc.y, sh.y), 0.f);
                v.z = fmaxf(fmaf(v.z, sc.z, sh.z), 0.f);
                v.w = fmaxf(fmaf(v.w, sc.w, sh.w), 0.f);
            }
            float f[4] = {v.x, v.y, v.z, v.w};
            __half h[4], l[4];
#pragma unroll
            for (int q = 0; q < 4; q++) {
                h[q] = __float2half_rn(f[q]);
                l[q] = __float2half_rn(f[q] - __half2float(h[q]));
            }
            uint2 uh, ul;
            ((__half2*)&uh)[0] = __halves2half2(h[0], h[1]);
            ((__half2*)&uh)[1] = __halves2half2(h[2], h[3]);
            ((__half2*)&ul)[0] = __halves2half2(l[0], l[1]);
            ((__half2*)&ul)[1] = __halves2half2(l[2], l[3]);
            *(uint2*)&Ah[row][c4 * 4] = uh;
            *(uint2*)&Al[row][c4 * 4] = ul;
        }
        // ---- stage B tile (already split & transposed: [BN][K]) ----
#pragma unroll
        for (int i = 0; i < (BN * 4 + 255) / 256; i++) {
            int idx = tid + i * 256;
            if (idx < BN * 4) {
                int n  = idx >> 2;
                int c8 = idx & 3;
                *(uint4*)&Bh[n][c8 * 8] = *(const uint4*)(Wh + (size_t)n * K + k0 + c8 * 8);
                *(uint4*)&Bl[n][c8 * 8] = *(const uint4*)(Wl + (size_t)n * K + k0 + c8 * 8);
            }
        }
        __syncthreads();

#pragma unroll
        for (int kk = 0; kk < BK; kk += 16) {
            uint32_t ah[MT][4], al[MT][4], bh[NT][2], bl[NT][2];
#pragma unroll
            for (int mt = 0; mt < MT; mt++) {
                int r = wmi * 64 + mt * 16 + g;
                ah[mt][0] = *(const uint32_t*)&Ah[r][kk + t4 * 2];
                ah[mt][1] = *(const uint32_t*)&Ah[r + 8][kk + t4 * 2];
                ah[mt][2] = *(const uint32_t*)&Ah[r][kk + t4 * 2 + 8];
                ah[mt][3] = *(const uint32_t*)&Ah[r + 8][kk + t4 * 2 + 8];
                al[mt][0] = *(const uint32_t*)&Al[r][kk + t4 * 2];
                al[mt][1] = *(const uint32_t*)&Al[r + 8][kk + t4 * 2];
                al[mt][2] = *(const uint32_t*)&Al[r][kk + t4 * 2 + 8];
                al[mt][3] = *(const uint32_t*)&Al[r + 8][kk + t4 * 2 + 8];
            }
#pragma unroll
            for (int nt = 0; nt < NT; nt++) {
                int n = wni * WNW + nt * 8 + g;
                bh[nt][0] = *(const uint32_t*)&Bh[n][kk + t4 * 2];
                bh[nt][1] = *(const uint32_t*)&Bh[n][kk + t4 * 2 + 8];
                bl[nt][0] = *(const uint32_t*)&Bl[n][kk + t4 * 2];
                bl[nt][1] = *(const uint32_t*)&Bl[n][kk + t4 * 2 + 8];
            }
#pragma unroll
            for (int mt = 0; mt < MT; mt++)
#pragma unroll
                for (int nt = 0; nt < NT; nt++) {
                    mma16816(acc[mt][nt], ah[mt], bh[nt]);
                    mma16816(acc[mt][nt], ah[mt], bl[nt]);
                    mma16816(acc[mt][nt], al[mt], bh[nt]);
                }
        }
        __syncthreads();
    }

    // ---- epilogue: scale by dis, convert to fp16, store ----
#pragma unroll
    for (int mt = 0; mt < MT; mt++) {
#pragma unroll
        for (int nt = 0; nt < NT; nt++) {
            int r0 = m0 + wmi * 64 + mt * 16 + g;
            int r1 = r0 + 8;
            int c  = wni * WNW + nt * 8 + t4 * 2;
            if (r0 < M) {
                float d = __ldg(disv + r0);
                *(__half2*)&C16[(size_t)r0 * BN + c] =
                    __floats2half2_rn(acc[mt][nt][0] * d, acc[mt][nt][1] * d);
            }
            if (r1 < M) {
                float d = __ldg(disv + r1);
                *(__half2*)&C16[(size_t)r1 * BN + c] =
                    __floats2half2_rn(acc[mt][nt][2] * d, acc[mt][nt][3] * d);
            }
        }
    }
}

// ---------------------------------------------------------------------------
// CSR gather on fp16 prescaled rows + FUSED BN statistics:
//   agg[i] = dis[i] * ( sum_nbr h16[src] + h16[i] ) + bias
//   stats[f]   += sum_i agg[i][f]        (via warp-shuffle + smem + RED)
//   stats[F+f] += sum_i agg[i][f]^2
// ---------------------------------------------------------------------------
template <int F>
__global__ __launch_bounds__(256) void k_gather16(
    const int* __restrict__ rowptr, const int* __restrict__ deg,
    const int* __restrict__ csr_src, const __half* __restrict__ h16,
    const float* __restrict__ dis, const float* __restrict__ bias,
    float* __restrict__ agg, float* __restrict__ stats, int N)
{
    constexpr int G = F / 8;            // lanes per node (4, 8, or 16)
    __shared__ float ssum[F];
    __shared__ float ssq[F];
    const int tid = threadIdx.x;
    if (tid < F) { ssum[tid] = 0.0f; ssq[tid] = 0.0f; }
    __syncthreads();

    int t    = blockIdx.x * 256 + tid;
    int node = t / G;
    int j    = t - node * G;
    const bool valid = node < N;
    const int cn = valid ? node : 0;

    int start = __ldg(rowptr + cn);
    int cnt   = valid ? __ldg(deg + cn) : 0;
    const __half* base = h16 + j * 8;

    float a[8];
#pragma unroll
    for (int q = 0; q < 8; q++) a[q] = 0.0f;

    auto addrow = [&](int s) {
        uint4 v = __ldg((const uint4*)(base + (size_t)s * F));
        const __half2* hv = (const __half2*)&v;
#pragma unroll
        for (int q = 0; q < 4; q++) {
            float2 f = __half22float2(hv[q]);
            a[2 * q]     += f.x;
            a[2 * q + 1] += f.y;
        }
    };

    int p = 0;
    for (; p + 2 <= cnt; p += 2) {
        int s0 = __ldg(csr_src + start + p);
        int s1 = __ldg(csr_src + start + p + 1);
        addrow(s0);
        addrow(s1);
    }
    if (p < cnt) addrow(__ldg(csr_src + start + p));
    if (valid) addrow(cn);   // self-loop (row already prescaled by dis[node])

    float d = valid ? __ldg(dis + cn) : 0.0f;
    float4 b0 = __ldg((const float4*)(bias + j * 8));
    float4 b1 = __ldg((const float4*)(bias + j * 8) + 1);
    float r[8];
    r[0] = fmaf(d, a[0], b0.x); r[1] = fmaf(d, a[1], b0.y);
    r[2] = fmaf(d, a[2], b0.z); r[3] = fmaf(d, a[3], b0.w);
    r[4] = fmaf(d, a[4], b1.x); r[5] = fmaf(d, a[5], b1.y);
    r[6] = fmaf(d, a[6], b1.z); r[7] = fmaf(d, a[7], b1.w);

    if (valid) {
        float4* o = (float4*)(agg + (size_t)node * F + j * 8);
        o[0] = make_float4(r[0], r[1], r[2], r[3]);
        o[1] = make_float4(r[4], r[5], r[6], r[7]);
    } else {
#pragma unroll
        for (int q = 0; q < 8; q++) r[q] = 0.0f;
    }

    // BN stats: reduce across same-j lanes of the warp, then smem bins
    float s2[8];
#pragma unroll
    for (int q = 0; q < 8; q++) s2[q] = r[q] * r[q];
#pragma unroll
    for (int o = 16; o >= G; o >>= 1) {
#pragma unroll
        for (int q = 0; q < 8; q++) {
            r[q]  += __shfl_xor_sync(0xFFFFFFFFu, r[q],  o);
            s2[q] += __shfl_xor_sync(0xFFFFFFFFu, s2[q], o);
        }
    }
    int lane = tid & 31;
    if (lane < G) {
#pragma unroll
        for (int q = 0; q < 8; q++) {
            atomicAdd(&ssum[lane * 8 + q], r[q]);
            atomicAdd(&ssq[lane * 8 + q],  s2[q]);
        }
    }
    __syncthreads();
    if (tid < F) {
        atomicAdd(&stats[tid],     ssum[tid]);
        atomicAdd(&stats[F + tid], ssq[tid]);
    }
}

// ---------------------------------------------------------------------------
// BN finalize: compute scale/shift, then RE-ZERO stats for the next layer
// ---------------------------------------------------------------------------
__global__ void k_bn_finalize(float* __restrict__ stats,
                              const float* __restrict__ g, const float* __restrict__ bt,
                              float* __restrict__ bnp, int N, int F)
{
    int f = threadIdx.x;
    if (f >= F) return;
    float inv_n = 1.0f / (float)N;
    float mu  = stats[f] * inv_n;
    float var = fmaxf(stats[F + f] * inv_n - mu * mu, 0.0f);
    float sc = g[f] * rsqrtf(var + 1e-5f);
    bnp[f]     = sc;
    bnp[F + f] = bt[f] - mu * sc;
    stats[f]     = 0.0f;
    stats[F + f] = 0.0f;
}

// ---------------------------------------------------------------------------
// Final FC with fused BN+ReLU
// ---------------------------------------------------------------------------
__global__ void k_final_fc(const float* __restrict__ h, const float* __restrict__ bnp,
                           const float* __restrict__ W, const float* __restrict__ b,
                           float* __restrict__ out, int N)
{
    int lane = threadIdx.x & 31;
    int node = (blockIdx.x * blockDim.x + threadIdx.x) >> 5;
    if (node >= N) return;
    float sc = __ldg(bnp + lane);
    float sh = __ldg(bnp + 32 + lane);
    float v = fmaxf(fmaf(h[(size_t)node * 32 + lane], sc, sh), 0.0f) * __ldg(W + lane);
#pragma unroll
    for (int o = 16; o; o >>= 1) v += __shfl_down_sync(0xFFFFFFFFu, v, o);
    if (lane == 0) out[node] = v + __ldg(b);
}

// ---------------------------------------------------------------------------
static inline int cdiv(long long a, long long b) { return (int)((a + b - 1) / b); }

extern "C" void kernel_launch(void* const* d_in, const int* in_sizes, int n_in,
                              void* d_out, int out_size)
{
    const float* x   = (const float*)d_in[0];
    const int*   ei  = (const int*)d_in[1];
    const float* W1  = (const float*)d_in[2];
    const float* b1  = (const float*)d_in[3];
    const float* g1  = (const float*)d_in[4];
    const float* bt1 = (const float*)d_in[5];
    const float* W2  = (const float*)d_in[6];
    const float* b2  = (const float*)d_in[7];
    const float* g2  = (const float*)d_in[8];
    const float* bt2 = (const float*)d_in[9];
    const float* W3  = (const float*)d_in[10];
    const float* b3  = (const float*)d_in[11];
    const float* g3  = (const float*)d_in[12];
    const float* bt3 = (const float*)d_in[13];
    const float* Wfc = (const float*)d_in[14];
    const float* bfc = (const float*)d_in[15];
    float* out = (float*)d_out;

    const int N = in_sizes[0] / 256;
    const int E = in_sizes[1] / 2;

    float *agg, *dis, *stats, *bnp;
    __half *h16, *whi, *wlo;
    int *deg, *rowptr, *cursor, *bsum, *csr;
    cudaGetSymbolAddress((void**)&agg,    g_agg);
    cudaGetSymbolAddress((void**)&h16,    g_h16);
    cudaGetSymbolAddress((void**)&dis,    g_dis);
    cudaGetSymbolAddress((void**)&deg,    g_deg);
    cudaGetSymbolAddress((void**)&rowptr, g_rowptr);
    cudaGetSymbolAddress((void**)&cursor, g_cursor);
    cudaGetSymbolAddress((void**)&bsum,   g_bsum);
    cudaGetSymbolAddress((void**)&csr,    g_csr_src);
    cudaGetSymbolAddress((void**)&stats,  g_stats);
    cudaGetSymbolAddress((void**)&bnp,    g_bnp);
    cudaGetSymbolAddress((void**)&whi,    g_whi);
    cudaGetSymbolAddress((void**)&wlo,    g_wlo);

    // ---- weight split (independent of everything else) ----
    k_splitW_all<<<cdiv(W3_OFF + 64 * 32, 256), 256>>>(W1, W2, W3, whi, wlo);

    // ---- degree / dis / CSR (scan_add2 also zeroes stats) ----
    k_zero_int<<<cdiv(N, 256), 256>>>(deg, N);
    k_count_deg<<<cdiv(E, 256), 256>>>(ei, deg, E);
    k_dis<<<cdiv(N, 256), 256>>>(deg, dis, N);
    int nb = cdiv(N, 1024);
    k_scan_block<<<nb, 1024>>>(deg, rowptr, bsum, N);
    k_scan_bsum<<<1, 256>>>(bsum, nb);
    k_scan_add2<<<cdiv(N, 256), 256>>>(rowptr, cursor, bsum, stats, N);
    k_csr_scatter<<<cdiv(E, 256), 256>>>(ei, cursor, csr, E);

    // ================= Layer 1: 256 -> 128 =================
    {
        constexpr int F = 128;
        k_mma_gemm<128><<<cdiv(N, 128), 256>>>(x, whi, wlo, h16, dis, N, 256, nullptr);
        k_gather16<F><<<cdiv((long long)N * (F / 8), 256), 256>>>(rowptr, deg, csr, h16, dis, b1, agg, stats, N);
        k_bn_finalize<<<1, F>>>(stats, g1, bt1, bnp, N, F);
    }
    // ================= Layer 2: 128 -> 64 =================
    {
        constexpr int F = 64;
        k_mma_gemm<64><<<cdiv(N, 128), 256>>>(agg, whi + W2_OFF, wlo + W2_OFF, h16, dis, N, 128, bnp);
        k_gather16<F><<<cdiv((long long)N * (F / 8), 256), 256>>>(rowptr, deg, csr, h16, dis, b2, agg, stats, N);
        k_bn_finalize<<<1, F>>>(stats, g2, bt2, bnp, N, F);
    }
    // ================= Layer 3: 64 -> 32 =================
    {
        constexpr int F = 32;
        k_mma_gemm<32><<<cdiv(N, 128), 256>>>(agg, whi + W3_OFF, wlo + W3_OFF, h16, dis, N, 64, bnp);
        k_gather16<F><<<cdiv((long long)N * (F / 8), 256), 256>>>(rowptr, deg, csr, h16, dis, b3, agg, stats, N);
        k_bn_finalize<<<1, F>>>(stats, g3, bt3, bnp, N, F);
    }
    // ================= Final FC: 32 -> 1 (fused BN+ReLU) =================
    k_final_fc<<<cdiv((long long)N * 32, 256), 256>>>(agg, bnp, Wfc, bfc, out, N);
}

// round 8
// speedup vs baseline: 2.8421x; 1.0690x over previous
#include <cuda_runtime.h>
#include <cuda_fp16.h>
#include <cuda_bf16.h>
#include <cstdint>

#define MAXN 100000
#define MAXE 3200000
#define MAXF 128

#define W2_OFF (256 * 128)
#define W3_OFF (256 * 128 + 128 * 64)
#define WTOT   (256 * 128 + 128 * 64 + 64 * 32)

// stats regions: [0,256) layer1 (F=128), [256,384) layer2 (F=64), [384,448) layer3 (F=32)
#define ST2 256
#define ST3 384
#define STTOT 448

// Scratch (device globals; no cudaMalloc allowed)
__device__ float  g_agg[(size_t)MAXN * MAXF];
__device__ __half g_h16[(size_t)MAXN * MAXF];
__device__ float  g_dis[MAXN];
__device__ int    g_deg[MAXN];
__device__ int    g_rowptr[MAXN + 1];
__device__ int    g_cursor[MAXN + 1];
__device__ int    g_bsum[256];
__device__ int    g_csr_src[MAXE];
__device__ float  g_stats[STTOT];
__device__ __half g_whi[WTOT];
__device__ __half g_wlo[WTOT];

// ---------------------------------------------------------------------------
// Prologue 1: fused degree count + weight split (independent, block-ranged)
// ---------------------------------------------------------------------------
__global__ void k_pro1(const int* __restrict__ ei, int* __restrict__ deg, int E, int nsc,
                       const float* __restrict__ W1, const float* __restrict__ W2,
                       const float* __restrict__ W3,
                       __half* __restrict__ Wh, __half* __restrict__ Wl)
{
    if ((int)blockIdx.x < nsc) {
        int e = blockIdx.x * 256 + threadIdx.x;
        if (e < E) atomicAdd(&deg[__ldg(ei + E + e)], 1);
        return;
    }
    int i = (blockIdx.x - nsc) * 256 + threadIdx.x;
    const float* W;
    int K, Nn, off, li;
    if (i < W2_OFF)       { W = W1; K = 256; Nn = 128; off = 0;      li = i; }
    else if (i < W3_OFF)  { W = W2; K = 128; Nn = 64;  off = W2_OFF; li = i - W2_OFF; }
    else if (i < WTOT)    { W = W3; K = 64;  Nn = 32;  off = W3_OFF; li = i - W3_OFF; }
    else return;
    int n = li / K, k = li - n * K;
    float v = __ldg(W + (size_t)k * Nn + n);
    __half h = __float2half_rn(v);
    Wh[off + li] = h;
    Wl[off + li] = __float2half_rn(v - __half2float(h));
}

// ---------------------------------------------------------------------------
// Scan (exclusive) of deg -> rowptr; also emits dis = rsqrt(deg+1)
// ---------------------------------------------------------------------------
__global__ void k_scan_block(const int* __restrict__ deg, int* __restrict__ exc,
                             int* __restrict__ bsum, float* __restrict__ dis, int N)
{
    __shared__ int sh[1024];
    int i = blockIdx.x * 1024 + threadIdx.x;
    int v = (i < N) ? deg[i] : 0;
    sh[threadIdx.x] = v;
    __syncthreads();
#pragma unroll
    for (int o = 1; o < 1024; o <<= 1) {
        int t = (threadIdx.x >= o) ? sh[threadIdx.x - o] : 0;
        __syncthreads();
        sh[threadIdx.x] += t;
        __syncthreads();
    }
    if (i < N) {
        exc[i] = sh[threadIdx.x] - v;
        dis[i] = rsqrtf((float)v + 1.0f);
    }
    if (threadIdx.x == 1023) bsum[blockIdx.x] = sh[1023];
}
__global__ void k_scan_bsum(int* bsum, int nb)
{
    __shared__ int sh[256];
    int t = threadIdx.x;
    int v = (t < nb) ? bsum[t] : 0;
    sh[t] = v;
    __syncthreads();
#pragma unroll
    for (int o = 1; o < 256; o <<= 1) {
        int u = (t >= o) ? sh[t - o] : 0;
        __syncthreads();
        sh[t] += u;
        __syncthreads();
    }
    if (t < nb) bsum[t] = sh[t] - v;   // exclusive
}
// adds block offsets, mirrors rowptr->cursor, zeroes ALL BN stats regions
__global__ void k_scan_add2(int* __restrict__ rowptr, int* __restrict__ cursor,
                            const int* __restrict__ bsum, float* __restrict__ stats, int N)
{
    int i = blockIdx.x * blockDim.x + threadIdx.x;
    if (i < N) {
        int v = rowptr[i] + bsum[i >> 10];
        rowptr[i] = v;
        cursor[i] = v;
    }
    if (blockIdx.x == 0) {
        for (int f = threadIdx.x; f < STTOT; f += 256) stats[f] = 0.0f;
    }
}

// ---------------------------------------------------------------------------
// Split-fp16 tensor-core GEMM core (device body):
//   C16[M,BN] = half( dis[m] * (BNReLU?(A[M,K]) @ W[K,BN]) )
// BN scale/shift computed IN-KERNEL from raw stats (if stats != nullptr).
// Computes AhiWhi + AhiWlo + AloWhi  (fp32-accurate to ~2^-22).
// BM=128, BK=32, 256 threads (8 warps as 2x4), warp tile 64 x (BN/4).
// ---------------------------------------------------------------------------
__device__ __forceinline__ void mma16816(float* c, const uint32_t* a, const uint32_t* b)
{
    asm volatile(
        "mma.sync.aligned.m16n8k16.row.col.f32.f16.f16.f32 "
        "{%0,%1,%2,%3}, {%4,%5,%6,%7}, {%8,%9}, {%0,%1,%2,%3};"
        : "+f"(c[0]), "+f"(c[1]), "+f"(c[2]), "+f"(c[3])
        : "r"(a[0]), "r"(a[1]), "r"(a[2]), "r"(a[3]), "r"(b[0]), "r"(b[1]));
}

template <int BN>
__device__ __forceinline__ void gemm_body(
    int bid, const float* __restrict__ A, const __half* __restrict__ Wh,
    const __half* __restrict__ Wl, __half* __restrict__ C16,
    const float* __restrict__ disv, int M, int K,
    const float* __restrict__ stats, const float* __restrict__ gam,
    const float* __restrict__ bt)
{
    constexpr int BM = 128, BK = 32;
    constexpr int LDA = BK + 8;           // halfs; 80B row stride
    constexpr int MT = 4;
    constexpr int NT = BN / 32;
    constexpr int WNW = BN / 4;

    __shared__ __align__(16) __half Ah[BM][LDA];
    __shared__ __align__(16) __half Al[BM][LDA];
    __shared__ __align__(16) __half Bh[BN][LDA];
    __shared__ __align__(16) __half Bl[BN][LDA];
    __shared__ __align__(16) float bnp_s[512];   // [K] scale | [K] shift (K<=128 when used)

    const int tid  = threadIdx.x;
    const int warp = tid >> 5;
    const int lane = tid & 31;
    const int g    = lane >> 2;
    const int t4   = lane & 3;
    const int wmi  = warp & 1;
    const int wni  = warp >> 1;
    const int m0   = bid * BM;
    const bool has_bn = (stats != nullptr);

    if (has_bn) {
        float inv_n = 1.0f / (float)M;
        for (int f = tid; f < K; f += 256) {
            float mu  = stats[f] * inv_n;
            float var = fmaxf(stats[K + f] * inv_n - mu * mu, 0.0f);
            float sc  = gam[f] * rsqrtf(var + 1e-5f);
            bnp_s[f]     = sc;
            bnp_s[K + f] = bt[f] - mu * sc;
        }
    }
    __syncthreads();

    float acc[MT][NT][4];
#pragma unroll
    for (int mt = 0; mt < MT; mt++)
#pragma unroll
        for (int nt = 0; nt < NT; nt++)
#pragma unroll
            for (int q = 0; q < 4; q++) acc[mt][nt][q] = 0.0f;

    for (int k0 = 0; k0 < K; k0 += BK) {
        // ---- stage A tile (fp32 -> hi/lo fp16), fused BN+ReLU ----
#pragma unroll
        for (int i = 0; i < 4; i++) {
            int idx = tid + i * 256;
            int row = idx >> 3;
            int c4  = idx & 7;
            float4 v = make_float4(0.f, 0.f, 0.f, 0.f);
            int gr = m0 + row;
            if (gr < M)
                v = *(const float4*)(A + (size_t)gr * K + k0 + c4 * 4);
            if (has_bn) {
                int kidx = k0 + c4 * 4;
                float4 sc = *(const float4*)&bnp_s[kidx];
                float4 sh = *(const float4*)&bnp_s[K + kidx];
                v.x = fmaxf(fmaf(v.x, sc.x, sh.x), 0.f);
                v.y = fmaxf(fmaf(v.y, sc.y, sh.y), 0.f);
                v.z = fmaxf(fmaf(v.z, sc.z, sh.z), 0.f);
                v.w = fmaxf(fmaf(v.w, sc.w, sh.w), 0.f);
            }
            float f[4] = {v.x, v.y, v.z, v.w};
            __half h[4], l[4];
#pragma unroll
            for (int q = 0; q < 4; q++) {
                h[q] = __float2half_rn(f[q]);
                l[q] = __float2half_rn(f[q] - __half2float(h[q]));
            }
            uint2 uh, ul;
            ((__half2*)&uh)[0] = __halves2half2(h[0], h[1]);
            ((__half2*)&uh)[1] = __halves2half2(h[2], h[3]);
            ((__half2*)&ul)[0] = __halves2half2(l[0], l[1]);
            ((__half2*)&ul)[1] = __halves2half2(l[2], l[3]);
            *(uint2*)&Ah[row][c4 * 4] = uh;
            *(uint2*)&Al[row][c4 * 4] = ul;
        }
        // ---- stage B tile (already split & transposed: [BN][K]) ----
#pragma unroll
        for (int i = 0; i < (BN * 4 + 255) / 256; i++) {
            int idx = tid + i * 256;
            if (idx < BN * 4) {
                int n  = idx >> 2;
                int c8 = idx & 3;
                *(uint4*)&Bh[n][c8 * 8] = *(const uint4*)(Wh + (size_t)n * K + k0 + c8 * 8);
                *(uint4*)&Bl[n][c8 * 8] = *(const uint4*)(Wl + (size_t)n * K + k0 + c8 * 8);
            }
        }
        __syncthreads();

#pragma unroll
        for (int kk = 0; kk < BK; kk += 16) {
            uint32_t ah[MT][4], al[MT][4], bh[NT][2], bl[NT][2];
#pragma unroll
            for (int mt = 0; mt < MT; mt++) {
                int r = wmi * 64 + mt * 16 + g;
                ah[mt][0] = *(const uint32_t*)&Ah[r][kk + t4 * 2];
                ah[mt][1] = *(const uint32_t*)&Ah[r + 8][kk + t4 * 2];
                ah[mt][2] = *(const uint32_t*)&Ah[r][kk + t4 * 2 + 8];
                ah[mt][3] = *(const uint32_t*)&Ah[r + 8][kk + t4 * 2 + 8];
                al[mt][0] = *(const uint32_t*)&Al[r][kk + t4 * 2];
                al[mt][1] = *(const uint32_t*)&Al[r + 8][kk + t4 * 2];
                al[mt][2] = *(const uint32_t*)&Al[r][kk + t4 * 2 + 8];
                al[mt][3] = *(const uint32_t*)&Al[r + 8][kk + t4 * 2 + 8];
            }
#pragma unroll
            for (int nt = 0; nt < NT; nt++) {
                int n = wni * WNW + nt * 8 + g;
                bh[nt][0] = *(const uint32_t*)&Bh[n][kk + t4 * 2];
                bh[nt][1] = *(const uint32_t*)&Bh[n][kk + t4 * 2 + 8];
                bl[nt][0] = *(const uint32_t*)&Bl[n][kk + t4 * 2];
                bl[nt][1] = *(const uint32_t*)&Bl[n][kk + t4 * 2 + 8];
            }
#pragma unroll
            for (int mt = 0; mt < MT; mt++)
#pragma unroll
                for (int nt = 0; nt < NT; nt++) {
                    mma16816(acc[mt][nt], ah[mt], bh[nt]);
                    mma16816(acc[mt][nt], ah[mt], bl[nt]);
                    mma16816(acc[mt][nt], al[mt], bh[nt]);
                }
        }
        __syncthreads();
    }

    // ---- epilogue: scale by dis, convert to fp16, store ----
#pragma unroll
    for (int mt = 0; mt < MT; mt++) {
#pragma unroll
        for (int nt = 0; nt < NT; nt++) {
            int r0 = m0 + wmi * 64 + mt * 16 + g;
            int r1 = r0 + 8;
            int c  = wni * WNW + nt * 8 + t4 * 2;
            if (r0 < M) {
                float d = __ldg(disv + r0);
                *(__half2*)&C16[(size_t)r0 * BN + c] =
                    __floats2half2_rn(acc[mt][nt][0] * d, acc[mt][nt][1] * d);
            }
            if (r1 < M) {
                float d = __ldg(disv + r1);
                *(__half2*)&C16[(size_t)r1 * BN + c] =
                    __floats2half2_rn(acc[mt][nt][2] * d, acc[mt][nt][3] * d);
            }
        }
    }
}

template <int BN>
__global__ __launch_bounds__(256) void k_mma_gemm(
    const float* __restrict__ A, const __half* __restrict__ Wh,
    const __half* __restrict__ Wl, __half* __restrict__ C16,
    const float* __restrict__ disv, int M, int K,
    const float* __restrict__ stats, const float* __restrict__ gam,
    const float* __restrict__ bt)
{
    gemm_body<BN>(blockIdx.x, A, Wh, Wl, C16, disv, M, K, stats, gam, bt);
}

// Fused CSR scatter + layer-1 GEMM (independent work, interleaved block stripe)
__global__ __launch_bounds__(256) void k_scatter_gemm1(
    const int* __restrict__ ei, int* __restrict__ cursor, int* __restrict__ csr_src,
    int E, int ngemm,
    const float* __restrict__ A, const __half* __restrict__ Wh,
    const __half* __restrict__ Wl, __half* __restrict__ C16,
    const float* __restrict__ disv, int M)
{
    int b = blockIdx.x;
    bool is_gemm;
    int id;
    if (b < 2 * ngemm) { is_gemm = (b & 1); id = b >> 1; }
    else               { is_gemm = false;   id = b - ngemm; }
    if (!is_gemm) {
        int e = id * 256 + threadIdx.x;
        if (e < E) {
            int src = __ldg(ei + e);
            int dst = __ldg(ei + E + e);
            int pos = atomicAdd(&cursor[dst], 1);
            csr_src[pos] = src;
        }
        return;
    }
    gemm_body<128>(id, A, Wh, Wl, C16, disv, M, 256, nullptr, nullptr, nullptr);
}

// ---------------------------------------------------------------------------
// CSR gather on fp16 prescaled rows + fused BN statistics into a region
// ---------------------------------------------------------------------------
template <int F>
__global__ __launch_bounds__(256) void k_gather16(
    const int* __restrict__ rowptr, const int* __restrict__ deg,
    const int* __restrict__ csr_src, const __half* __restrict__ h16,
    const float* __restrict__ dis, const float* __restrict__ bias,
    float* __restrict__ agg, float* __restrict__ stats, int N)
{
    constexpr int G = F / 8;
    __shared__ float ssum[F];
    __shared__ float ssq[F];
    const int tid = threadIdx.x;
    if (tid < F) { ssum[tid] = 0.0f; ssq[tid] = 0.0f; }
    __syncthreads();

    int t    = blockIdx.x * 256 + tid;
    int node = t / G;
    int j    = t - node * G;
    const bool valid = node < N;
    const int cn = valid ? node : 0;

    int start = __ldg(rowptr + cn);
    int cnt   = valid ? __ldg(deg + cn) : 0;
    const __half* base = h16 + j * 8;

    float a[8];
#pragma unroll
    for (int q = 0; q < 8; q++) a[q] = 0.0f;

    auto addrow = [&](int s) {
        uint4 v = __ldg((const uint4*)(base + (size_t)s * F));
        const __half2* hv = (const __half2*)&v;
#pragma unroll
        for (int q = 0; q < 4; q++) {
            float2 f = __half22float2(hv[q]);
            a[2 * q]     += f.x;
            a[2 * q + 1] += f.y;
        }
    };

    int p = 0;
    for (; p + 2 <= cnt; p += 2) {
        int s0 = __ldg(csr_src + start + p);
        int s1 = __ldg(csr_src + start + p + 1);
        addrow(s0);
        addrow(s1);
    }
    if (p < cnt) addrow(__ldg(csr_src + start + p));
    if (valid) addrow(cn);   // self-loop (row already prescaled by dis[node])

    float d = valid ? __ldg(dis + cn) : 0.0f;
    float4 b0 = __ldg((const float4*)(bias + j * 8));
    float4 b1 = __ldg((const float4*)(bias + j * 8) + 1);
    float r[8];
    r[0] = fmaf(d, a[0], b0.x); r[1] = fmaf(d, a[1], b0.y);
    r[2] = fmaf(d, a[2], b0.z); r[3] = fmaf(d, a[3], b0.w);
    r[4] = fmaf(d, a[4], b1.x); r[5] = fmaf(d, a[5], b1.y);
    r[6] = fmaf(d, a[6], b1.z); r[7] = fmaf(d, a[7], b1.w);

    if (valid) {
        float4* o = (float4*)(agg + (size_t)node * F + j * 8);
        o[0] = make_float4(r[0], r[1], r[2], r[3]);
        o[1] = make_float4(r[4], r[5], r[6], r[7]);
    } else {
#pragma unroll
        for (int q = 0; q < 8; q++) r[q] = 0.0f;
    }

    float s2[8];
#pragma unroll
    for (int q = 0; q < 8; q++) s2[q] = r[q] * r[q];
#pragma unroll
    for (int o = 16; o >= G; o >>= 1) {
#pragma unroll
        for (int q = 0; q < 8; q++) {
            r[q]  += __shfl_xor_sync(0xFFFFFFFFu, r[q],  o);
            s2[q] += __shfl_xor_sync(0xFFFFFFFFu, s2[q], o);
        }
    }
    int lane = tid & 31;
    if (lane < G) {
#pragma unroll
        for (int q = 0; q < 8; q++) {
            atomicAdd(&ssum[lane * 8 + q], r[q]);
            atomicAdd(&ssq[lane * 8 + q],  s2[q]);
        }
    }
    __syncthreads();
    if (tid < F) {
        atomicAdd(&stats[tid],     ssum[tid]);
        atomicAdd(&stats[F + tid], ssq[tid]);
    }
}

// ---------------------------------------------------------------------------
// Final FC with in-kernel BN finalize + fused BN+ReLU
// ---------------------------------------------------------------------------
__global__ void k_final_fc(const float* __restrict__ h, const float* __restrict__ stats,
                           const float* __restrict__ gam, const float* __restrict__ bt,
                           const float* __restrict__ W, const float* __restrict__ b,
                           float* __restrict__ out, int N)
{
    __shared__ float sc_s[32], sh_s[32];
    int tid = threadIdx.x;
    if (tid < 32) {
        float inv_n = 1.0f / (float)N;
        float mu  = stats[tid] * inv_n;
        float var = fmaxf(stats[32 + tid] * inv_n - mu * mu, 0.0f);
        float sc  = gam[tid] * rsqrtf(var + 1e-5f);
        sc_s[tid] = sc;
        sh_s[tid] = bt[tid] - mu * sc;
    }
    __syncthreads();
    int lane = tid & 31;
    int node = (blockIdx.x * blockDim.x + tid) >> 5;
    if (node >= N) return;
    float v = fmaxf(fmaf(h[(size_t)node * 32 + lane], sc_s[lane], sh_s[lane]), 0.0f)
              * __ldg(W + lane);
#pragma unroll
    for (int o = 16; o; o >>= 1) v += __shfl_down_sync(0xFFFFFFFFu, v, o);
    if (lane == 0) out[node] = v + __ldg(b);
}

// ---------------------------------------------------------------------------
static inline int cdiv(long long a, long long b) { return (int)((a + b - 1) / b); }

extern "C" void kernel_launch(void* const* d_in, const int* in_sizes, int n_in,
                              void* d_out, int out_size)
{
    const float* x   = (const float*)d_in[0];
    const int*   ei  = (const int*)d_in[1];
    const float* W1  = (const float*)d_in[2];
    const float* b1  = (const float*)d_in[3];
    const float* g1  = (const float*)d_in[4];
    const float* bt1 = (const float*)d_in[5];
    const float* W2  = (const float*)d_in[6];
    const float* b2  = (const float*)d_in[7];
    const float* g2  = (const float*)d_in[8];
    const float* bt2 = (const float*)d_in[9];
    const float* W3  = (const float*)d_in[10];
    const float* b3  = (const float*)d_in[11];
    const float* g3  = (const float*)d_in[12];
    const float* bt3 = (const float*)d_in[13];
    const float* Wfc = (const float*)d_in[14];
    const float* bfc = (const float*)d_in[15];
    float* out = (float*)d_out;

    const int N = in_sizes[0] / 256;
    const int E = in_sizes[1] / 2;

    float *agg, *dis, *stats;
    __half *h16, *whi, *wlo;
    int *deg, *rowptr, *cursor, *bsum, *csr;
    cudaGetSymbolAddress((void**)&agg,    g_agg);
    cudaGetSymbolAddress((void**)&h16,    g_h16);
    cudaGetSymbolAddress((void**)&dis,    g_dis);
    cudaGetSymbolAddress((void**)&deg,    g_deg);
    cudaGetSymbolAddress((void**)&rowptr, g_rowptr);
    cudaGetSymbolAddress((void**)&cursor, g_cursor);
    cudaGetSymbolAddress((void**)&bsum,   g_bsum);
    cudaGetSymbolAddress((void**)&csr,    g_csr_src);
    cudaGetSymbolAddress((void**)&stats,  g_stats);
    cudaGetSymbolAddress((void**)&whi,    g_whi);
    cudaGetSymbolAddress((void**)&wlo,    g_wlo);

    const int nsc   = cdiv(E, 256);
    const int nw    = cdiv(WTOT, 256);
    const int nb    = cdiv(N, 1024);
    const int ngemm = cdiv(N, 128);

    // ---- prologue: degree count + weight split, scan(+dis), scatter+GEMM1 ----
    cudaMemsetAsync(deg, 0, (size_t)N * sizeof(int));
    k_pro1<<<nsc + nw, 256>>>(ei, deg, E, nsc, W1, W2, W3, whi, wlo);
    k_scan_block<<<nb, 1024>>>(deg, rowptr, bsum, dis, N);
    k_scan_bsum<<<1, 256>>>(bsum, nb);
    k_scan_add2<<<cdiv(N, 256), 256>>>(rowptr, cursor, bsum, stats, N);
    k_scatter_gemm1<<<ngemm + nsc, 256>>>(ei, cursor, csr, E, ngemm,
                                          x, whi, wlo, h16, dis, N);

    // ================= Layer 1 gather (F=128) =================
    k_gather16<128><<<cdiv((long long)N * 16, 256), 256>>>(
        rowptr, deg, csr, h16, dis, b1, agg, stats, N);

    // ================= Layer 2: 128 -> 64 =================
    k_mma_gemm<64><<<ngemm, 256>>>(agg, whi + W2_OFF, wlo + W2_OFF, h16, dis, N, 128,
                                   stats, g1, bt1);
    k_gather16<64><<<cdiv((long long)N * 8, 256), 256>>>(
        rowptr, deg, csr, h16, dis, b2, agg, stats + ST2, N);

    // ================= Layer 3: 64 -> 32 =================
    k_mma_gemm<32><<<ngemm, 256>>>(agg, whi + W3_OFF, wlo + W3_OFF, h16, dis, N, 64,
                                   stats + ST2, g2, bt2);
    k_gather16<32><<<cdiv((long long)N * 4, 256), 256>>>(
        rowptr, deg, csr, h16, dis, b3, agg, stats + ST3, N);

    // ================= Final FC: 32 -> 1 (in-kernel BN + ReLU) =================
    k_final_fc<<<cdiv((long long)N * 32, 256), 256>>>(agg, stats + ST3, g3, bt3,
                                                      Wfc, bfc, out, N);
}

// round 9
// speedup vs baseline: 3.0506x; 1.0734x over previous
#include <cuda_runtime.h>
#include <cuda_fp16.h>
#include <cuda_bf16.h>
#include <cstdint>

#define MAXN 100000
#define MAXE 3200000
#define MAXF 128

#define W2_OFF (256 * 128)
#define W3_OFF (256 * 128 + 128 * 64)
#define WTOT   (256 * 128 + 128 * 64 + 64 * 32)

// stats regions: [0,256) layer1 (F=128), [256,384) layer2 (F=64), [384,448) layer3 (F=32)
#define ST2 256
#define ST3 384
#define STTOT 448

// Scratch (device globals; no cudaMalloc allowed)
__device__ float  g_agg[(size_t)MAXN * MAXF];
__device__ __half g_h16[(size_t)MAXN * MAXF];
__device__ float  g_dis[MAXN];
__device__ int    g_deg[MAXN];
__device__ int    g_rowptr[MAXN + 1];
__device__ int    g_cursor[MAXN + 1];
__device__ int    g_bsum[256];
__device__ int    g_csr_src[MAXE];
__device__ float  g_stats[STTOT];
__device__ __half g_whi[WTOT];

// ---------------------------------------------------------------------------
// Prologue 1: fused degree count + weight fp16 round/transpose
// ---------------------------------------------------------------------------
__global__ void k_pro1(const int* __restrict__ ei, int* __restrict__ deg, int E, int nsc,
                       const float* __restrict__ W1, const float* __restrict__ W2,
                       const float* __restrict__ W3, __half* __restrict__ Wh)
{
    if ((int)blockIdx.x < nsc) {
        int e = blockIdx.x * 256 + threadIdx.x;
        if (e < E) atomicAdd(&deg[__ldg(ei + E + e)], 1);
        return;
    }
    int i = (blockIdx.x - nsc) * 256 + threadIdx.x;
    const float* W;
    int K, Nn, off, li;
    if (i < W2_OFF)       { W = W1; K = 256; Nn = 128; off = 0;      li = i; }
    else if (i < W3_OFF)  { W = W2; K = 128; Nn = 64;  off = W2_OFF; li = i - W2_OFF; }
    else if (i < WTOT)    { W = W3; K = 64;  Nn = 32;  off = W3_OFF; li = i - W3_OFF; }
    else return;
    int n = li / K, k = li - n * K;
    Wh[off + li] = __float2half_rn(__ldg(W + (size_t)k * Nn + n));
}

// ---------------------------------------------------------------------------
// Scan (exclusive) of deg -> rowptr; also emits dis = rsqrt(deg+1)
// ---------------------------------------------------------------------------
__global__ void k_scan_block(const int* __restrict__ deg, int* __restrict__ exc,
                             int* __restrict__ bsum, float* __restrict__ dis, int N)
{
    __shared__ int sh[1024];
    int i = blockIdx.x * 1024 + threadIdx.x;
    int v = (i < N) ? deg[i] : 0;
    sh[threadIdx.x] = v;
    __syncthreads();
#pragma unroll
    for (int o = 1; o < 1024; o <<= 1) {
        int t = (threadIdx.x >= o) ? sh[threadIdx.x - o] : 0;
        __syncthreads();
        sh[threadIdx.x] += t;
        __syncthreads();
    }
    if (i < N) {
        exc[i] = sh[threadIdx.x] - v;
        dis[i] = rsqrtf((float)v + 1.0f);
    }
    if (threadIdx.x == 1023) bsum[blockIdx.x] = sh[1023];
}

// Adds block offsets (bsum scanned redundantly per block in smem),
// mirrors rowptr->cursor, zeroes ALL BN stats regions.
__global__ void k_scan_add2(int* __restrict__ rowptr, int* __restrict__ cursor,
                            const int* __restrict__ bsum, float* __restrict__ stats,
                            int nb, int N)
{
    __shared__ int sh[256];
    __shared__ int sexc[256];
    int t = threadIdx.x;
    int v = (t < nb) ? __ldg(bsum + t) : 0;
    sh[t] = v;
    __syncthreads();
#pragma unroll
    for (int o = 1; o < 256; o <<= 1) {
        int u = (t >= o) ? sh[t - o] : 0;
        __syncthreads();
        sh[t] += u;
        __syncthreads();
    }
    sexc[t] = sh[t] - v;   // exclusive prefix of bsum
    __syncthreads();

    int i = blockIdx.x * 256 + t;
    if (i < N) {
        int val = rowptr[i] + sexc[i >> 10];
        rowptr[i] = val;
        cursor[i] = val;
    }
    if (blockIdx.x == 0) {
        for (int f = t; f < STTOT; f += 256) stats[f] = 0.0f;
    }
}

// ---------------------------------------------------------------------------
// 2-product split GEMM core:
//   C16[M,BN] = half( dis[m] * (BNReLU?(A[M,K]) @ W16[K,BN]) )
// A split in-register to hi+lo fp16 (exact to 2^-22); W fp16-rounded.
// Products: AhiWhi + AloWhi.  BN scale/shift computed in-kernel from stats.
// BM=128, BK=32, 256 threads (8 warps as 2x4), warp tile 64 x (BN/4).
// ---------------------------------------------------------------------------
__device__ __forceinline__ void mma16816(float* c, const uint32_t* a, const uint32_t* b)
{
    asm volatile(
        "mma.sync.aligned.m16n8k16.row.col.f32.f16.f16.f32 "
        "{%0,%1,%2,%3}, {%4,%5,%6,%7}, {%8,%9}, {%0,%1,%2,%3};"
        : "+f"(c[0]), "+f"(c[1]), "+f"(c[2]), "+f"(c[3])
        : "r"(a[0]), "r"(a[1]), "r"(a[2]), "r"(a[3]), "r"(b[0]), "r"(b[1]));
}

template <int BN>
__device__ __forceinline__ void gemm_body(
    int bid, const float* __restrict__ A, const __half* __restrict__ Wh,
    __half* __restrict__ C16, const float* __restrict__ disv, int M, int K,
    const float* __restrict__ stats, const float* __restrict__ gam,
    const float* __restrict__ bt)
{
    constexpr int BM = 128, BK = 32;
    constexpr int LDA = BK + 8;           // halfs; 80B row stride
    constexpr int MT = 4;
    constexpr int NT = BN / 32;
    constexpr int WNW = BN / 4;

    __shared__ __align__(16) __half Ah[BM][LDA];
    __shared__ __align__(16) __half Al[BM][LDA];
    __shared__ __align__(16) __half Bh[BN][LDA];
    __shared__ __align__(16) float bnp_s[512];   // [K] scale | [K] shift

    const int tid  = threadIdx.x;
    const int warp = tid >> 5;
    const int lane = tid & 31;
    const int g    = lane >> 2;
    const int t4   = lane & 3;
    const int wmi  = warp & 1;
    const int wni  = warp >> 1;
    const int m0   = bid * BM;
    const bool has_bn = (stats != nullptr);

    if (has_bn) {
        float inv_n = 1.0f / (float)M;
        for (int f = tid; f < K; f += 256) {
            float mu  = stats[f] * inv_n;
            float var = fmaxf(stats[K + f] * inv_n - mu * mu, 0.0f);
            float sc  = gam[f] * rsqrtf(var + 1e-5f);
            bnp_s[f]     = sc;
            bnp_s[K + f] = bt[f] - mu * sc;
        }
    }
    __syncthreads();

    float acc[MT][NT][4];
#pragma unroll
    for (int mt = 0; mt < MT; mt++)
#pragma unroll
        for (int nt = 0; nt < NT; nt++)
#pragma unroll
            for (int q = 0; q < 4; q++) acc[mt][nt][q] = 0.0f;

    for (int k0 = 0; k0 < K; k0 += BK) {
        // ---- stage A tile (fp32 -> hi/lo fp16), fused BN+ReLU ----
#pragma unroll
        for (int i = 0; i < 4; i++) {
            int idx = tid + i * 256;
            int row = idx >> 3;
            int c4  = idx & 7;
            float4 v = make_float4(0.f, 0.f, 0.f, 0.f);
            int gr = m0 + row;
            if (gr < M)
                v = *(const float4*)(A + (size_t)gr * K + k0 + c4 * 4);
            if (has_bn) {
                int kidx = k0 + c4 * 4;
                float4 sc = *(const float4*)&bnp_s[kidx];
                float4 sh = *(const float4*)&bnp_s[K + kidx];
                v.x = fmaxf(fmaf(v.x, sc.x, sh.x), 0.f);
                v.y = fmaxf(fmaf(v.y, sc.y, sh.y), 0.f);
                v.z = fmaxf(fmaf(v.z, sc.z, sh.z), 0.f);
                v.w = fmaxf(fmaf(v.w, sc.w, sh.w), 0.f);
            }
            float f[4] = {v.x, v.y, v.z, v.w};
            __half h[4], l[4];
#pragma unroll
            for (int q = 0; q < 4; q++) {
                h[q] = __float2half_rn(f[q]);
                l[q] = __float2half_rn(f[q] - __half2float(h[q]));
            }
            uint2 uh, ul;
            ((__half2*)&uh)[0] = __halves2half2(h[0], h[1]);
            ((__half2*)&uh)[1] = __halves2half2(h[2], h[3]);
            ((__half2*)&ul)[0] = __halves2half2(l[0], l[1]);
            ((__half2*)&ul)[1] = __halves2half2(l[2], l[3]);
            *(uint2*)&Ah[row][c4 * 4] = uh;
            *(uint2*)&Al[row][c4 * 4] = ul;
        }
        // ---- stage B tile (fp16, transposed [BN][K]) ----
#pragma unroll
        for (int i = 0; i < (BN * 4 + 255) / 256; i++) {
            int idx = tid + i * 256;
            if (idx < BN * 4) {
                int n  = idx >> 2;
                int c8 = idx & 3;
                *(uint4*)&Bh[n][c8 * 8] = *(const uint4*)(Wh + (size_t)n * K + k0 + c8 * 8);
            }
        }
        __syncthreads();

#pragma unroll
        for (int kk = 0; kk < BK; kk += 16) {
            uint32_t ah[MT][4], al[MT][4], bh[NT][2];
#pragma unroll
            for (int mt = 0; mt < MT; mt++) {
                int r = wmi * 64 + mt * 16 + g;
                ah[mt][0] = *(const uint32_t*)&Ah[r][kk + t4 * 2];
                ah[mt][1] = *(const uint32_t*)&Ah[r + 8][kk + t4 * 2];
                ah[mt][2] = *(const uint32_t*)&Ah[r][kk + t4 * 2 + 8];
                ah[mt][3] = *(const uint32_t*)&Ah[r + 8][kk + t4 * 2 + 8];
                al[mt][0] = *(const uint32_t*)&Al[r][kk + t4 * 2];
                al[mt][1] = *(const uint32_t*)&Al[r + 8][kk + t4 * 2];
                al[mt][2] = *(const uint32_t*)&Al[r][kk + t4 * 2 + 8];
                al[mt][3] = *(const uint32_t*)&Al[r + 8][kk + t4 * 2 + 8];
            }
#pragma unroll
            for (int nt = 0; nt < NT; nt++) {
                int n = wni * WNW + nt * 8 + g;
                bh[nt][0] = *(const uint32_t*)&Bh[n][kk + t4 * 2];
                bh[nt][1] = *(const uint32_t*)&Bh[n][kk + t4 * 2 + 8];
            }
#pragma unroll
            for (int mt = 0; mt < MT; mt++)
#pragma unroll
                for (int nt = 0; nt < NT; nt++) {
                    mma16816(acc[mt][nt], ah[mt], bh[nt]);
                    mma16816(acc[mt][nt], al[mt], bh[nt]);
                }
        }
        __syncthreads();
    }

    // ---- epilogue: scale by dis, convert to fp16, store ----
#pragma unroll
    for (int mt = 0; mt < MT; mt++) {
#pragma unroll
        for (int nt = 0; nt < NT; nt++) {
            int r0 = m0 + wmi * 64 + mt * 16 + g;
            int r1 = r0 + 8;
            int c  = wni * WNW + nt * 8 + t4 * 2;
            if (r0 < M) {
                float d = __ldg(disv + r0);
                *(__half2*)&C16[(size_t)r0 * BN + c] =
                    __floats2half2_rn(acc[mt][nt][0] * d, acc[mt][nt][1] * d);
            }
            if (r1 < M) {
                float d = __ldg(disv + r1);
                *(__half2*)&C16[(size_t)r1 * BN + c] =
                    __floats2half2_rn(acc[mt][nt][2] * d, acc[mt][nt][3] * d);
            }
        }
    }
}

template <int BN>
__global__ __launch_bounds__(256) void k_mma_gemm(
    const float* __restrict__ A, const __half* __restrict__ Wh,
    __half* __restrict__ C16, const float* __restrict__ disv, int M, int K,
    const float* __restrict__ stats, const float* __restrict__ gam,
    const float* __restrict__ bt)
{
    gemm_body<BN>(blockIdx.x, A, Wh, C16, disv, M, K, stats, gam, bt);
}

// Fused CSR scatter + layer-1 GEMM (independent work, interleaved block stripe)
__global__ __launch_bounds__(256) void k_scatter_gemm1(
    const int* __restrict__ ei, int* __restrict__ cursor, int* __restrict__ csr_src,
    int E, int ngemm,
    const float* __restrict__ A, const __half* __restrict__ Wh,
    __half* __restrict__ C16, const float* __restrict__ disv, int M)
{
    int b = blockIdx.x;
    bool is_gemm;
    int id;
    if (b < 2 * ngemm) { is_gemm = (b & 1); id = b >> 1; }
    else               { is_gemm = false;   id = b - ngemm; }
    if (!is_gemm) {
        int e = id * 256 + threadIdx.x;
        if (e < E) {
            int src = __ldg(ei + e);
            int dst = __ldg(ei + E + e);
            int pos = atomicAdd(&cursor[dst], 1);
            csr_src[pos] = src;
        }
        return;
    }
    gemm_body<128>(id, A, Wh, C16, disv, M, 256, nullptr, nullptr, nullptr);
}

// ---------------------------------------------------------------------------
// CSR gather on fp16 prescaled rows + fused BN statistics (4-edge unroll)
// ---------------------------------------------------------------------------
template <int F>
__global__ __launch_bounds__(256) void k_gather16(
    const int* __restrict__ rowptr, const int* __restrict__ deg,
    const int* __restrict__ csr_src, const __half* __restrict__ h16,
    const float* __restrict__ dis, const float* __restrict__ bias,
    float* __restrict__ agg, float* __restrict__ stats, int N)
{
    constexpr int G = F / 8;
    __shared__ float ssum[F];
    __shared__ float ssq[F];
    const int tid = threadIdx.x;
    if (tid < F) { ssum[tid] = 0.0f; ssq[tid] = 0.0f; }
    __syncthreads();

    int t    = blockIdx.x * 256 + tid;
    int node = t / G;
    int j    = t - node * G;
    const bool valid = node < N;
    const int cn = valid ? node : 0;

    int start = __ldg(rowptr + cn);
    int cnt   = valid ? __ldg(deg + cn) : 0;
    const __half* base = h16 + j * 8;

    float a[8];
#pragma unroll
    for (int q = 0; q < 8; q++) a[q] = 0.0f;

    auto addv = [&](uint4 v) {
        const __half2* hv = (const __half2*)&v;
#pragma unroll
        for (int q = 0; q < 4; q++) {
            float2 f = __half22float2(hv[q]);
            a[2 * q]     += f.x;
            a[2 * q + 1] += f.y;
        }
    };

    int p = 0;
    for (; p + 4 <= cnt; p += 4) {
        int s0 = __ldg(csr_src + start + p);
        int s1 = __ldg(csr_src + start + p + 1);
        int s2 = __ldg(csr_src + start + p + 2);
        int s3 = __ldg(csr_src + start + p + 3);
        uint4 v0 = __ldg((const uint4*)(base + (size_t)s0 * F));
        uint4 v1 = __ldg((const uint4*)(base + (size_t)s1 * F));
        uint4 v2 = __ldg((const uint4*)(base + (size_t)s2 * F));
        uint4 v3 = __ldg((const uint4*)(base + (size_t)s3 * F));
        addv(v0); addv(v1); addv(v2); addv(v3);
    }
    for (; p < cnt; p++) {
        int s = __ldg(csr_src + start + p);
        addv(__ldg((const uint4*)(base + (size_t)s * F)));
    }
    if (valid) addv(__ldg((const uint4*)(base + (size_t)cn * F)));  // self-loop

    float d = valid ? __ldg(dis + cn) : 0.0f;
    float4 b0 = __ldg((const float4*)(bias + j * 8));
    float4 b1 = __ldg((const float4*)(bias + j * 8) + 1);
    float r[8];
    r[0] = fmaf(d, a[0], b0.x); r[1] = fmaf(d, a[1], b0.y);
    r[2] = fmaf(d, a[2], b0.z); r[3] = fmaf(d, a[3], b0.w);
    r[4] = fmaf(d, a[4], b1.x); r[5] = fmaf(d, a[5], b1.y);
    r[6] = fmaf(d, a[6], b1.z); r[7] = fmaf(d, a[7], b1.w);

    if (valid) {
        float4* o = (float4*)(agg + (size_t)node * F + j * 8);
        o[0] = make_float4(r[0], r[1], r[2], r[3]);
        o[1] = make_float4(r[4], r[5], r[6], r[7]);
    } else {
#pragma unroll
        for (int q = 0; q < 8; q++) r[q] = 0.0f;
    }

    float s2v[8];
#pragma unroll
    for (int q = 0; q < 8; q++) s2v[q] = r[q] * r[q];
#pragma unroll
    for (int o = 16; o >= G; o >>= 1) {
#pragma unroll
        for (int q = 0; q < 8; q++) {
            r[q]   += __shfl_xor_sync(0xFFFFFFFFu, r[q],   o);
            s2v[q] += __shfl_xor_sync(0xFFFFFFFFu, s2v[q], o);
        }
    }
    int lane = tid & 31;
    if (lane < G) {
#pragma unroll
        for (int q = 0; q < 8; q++) {
            atomicAdd(&ssum[lane * 8 + q], r[q]);
            atomicAdd(&ssq[lane * 8 + q],  s2v[q]);
        }
    }
    __syncthreads();
    if (tid < F) {
        atomicAdd(&stats[tid],     ssum[tid]);
        atomicAdd(&stats[F + tid], ssq[tid]);
    }
}

// ---------------------------------------------------------------------------
// Final FC with in-kernel BN finalize + fused BN+ReLU
// ---------------------------------------------------------------------------
__global__ void k_final_fc(const float* __restrict__ h, const float* __restrict__ stats,
                           const float* __restrict__ gam, const float* __restrict__ bt,
                           const float* __restrict__ W, const float* __restrict__ b,
                           float* __restrict__ out, int N)
{
    __shared__ float sc_s[32], sh_s[32];
    int tid = threadIdx.x;
    if (tid < 32) {
        float inv_n = 1.0f / (float)N;
        float mu  = stats[tid] * inv_n;
        float var = fmaxf(stats[32 + tid] * inv_n - mu * mu, 0.0f);
        float sc  = gam[tid] * rsqrtf(var + 1e-5f);
        sc_s[tid] = sc;
        sh_s[tid] = bt[tid] - mu * sc;
    }
    __syncthreads();
    int lane = tid & 31;
    int node = (blockIdx.x * blockDim.x + tid) >> 5;
    if (node >= N) return;
    float v = fmaxf(fmaf(h[(size_t)node * 32 + lane], sc_s[lane], sh_s[lane]), 0.0f)
              * __ldg(W + lane);
#pragma unroll
    for (int o = 16; o; o >>= 1) v += __shfl_down_sync(0xFFFFFFFFu, v, o);
    if (lane == 0) out[node] = v + __ldg(b);
}

// ---------------------------------------------------------------------------
static inline int cdiv(long long a, long long b) { return (int)((a + b - 1) / b); }

extern "C" void kernel_launch(void* const* d_in, const int* in_sizes, int n_in,
                              void* d_out, int out_size)
{
    const float* x   = (const float*)d_in[0];
    const int*   ei  = (const int*)d_in[1];
    const float* W1  = (const float*)d_in[2];
    const float* b1  = (const float*)d_in[3];
    const float* g1  = (const float*)d_in[4];
    const float* bt1 = (const float*)d_in[5];
    const float* W2  = (const float*)d_in[6];
    const float* b2  = (const float*)d_in[7];
    const float* g2  = (const float*)d_in[8];
    const float* bt2 = (const float*)d_in[9];
    const float* W3  = (const float*)d_in[10];
    const float* b3  = (const float*)d_in[11];
    const float* g3  = (const float*)d_in[12];
    const float* bt3 = (const float*)d_in[13];
    const float* Wfc = (const float*)d_in[14];
    const float* bfc = (const float*)d_in[15];
    float* out = (float*)d_out;

    const int N = in_sizes[0] / 256;
    const int E = in_sizes[1] / 2;

    float *agg, *dis, *stats;
    __half *h16, *whi;
    int *deg, *rowptr, *cursor, *bsum, *csr;
    cudaGetSymbolAddress((void**)&agg,    g_agg);
    cudaGetSymbolAddress((void**)&h16,    g_h16);
    cudaGetSymbolAddress((void**)&dis,    g_dis);
    cudaGetSymbolAddress((void**)&deg,    g_deg);
    cudaGetSymbolAddress((void**)&rowptr, g_rowptr);
    cudaGetSymbolAddress((void**)&cursor, g_cursor);
    cudaGetSymbolAddress((void**)&bsum,   g_bsum);
    cudaGetSymbolAddress((void**)&csr,    g_csr_src);
    cudaGetSymbolAddress((void**)&stats,  g_stats);
    cudaGetSymbolAddress((void**)&whi,    g_whi);

    const int nsc   = cdiv(E, 256);
    const int nw    = cdiv(WTOT, 256);
    const int nb    = cdiv(N, 1024);
    const int ngemm = cdiv(N, 128);

    // ---- prologue: degree count + weight round, scan(+dis), scatter+GEMM1 ----
    cudaMemsetAsync(deg, 0, (size_t)N * sizeof(int));
    k_pro1<<<nsc + nw, 256>>>(ei, deg, E, nsc, W1, W2, W3, whi);
    k_scan_block<<<nb, 1024>>>(deg, rowptr, bsum, dis, N);
    k_scan_add2<<<cdiv(N, 256), 256>>>(rowptr, cursor, bsum, stats, nb, N);
    k_scatter_gemm1<<<ngemm + nsc, 256>>>(ei, cursor, csr, E, ngemm,
                                          x, whi, h16, dis, N);

    // ================= Layer 1 gather (F=128) =================
    k_gather16<128><<<cdiv((long long)N * 16, 256), 256>>>(
        rowptr, deg, csr, h16, dis, b1, agg, stats, N);

    // ================= Layer 2: 128 -> 64 =================
    k_mma_gemm<64><<<ngemm, 256>>>(agg, whi + W2_OFF, h16, dis, N, 128,
                                   stats, g1, bt1);
    k_gather16<64><<<cdiv((long long)N * 8, 256), 256>>>(
        rowptr, deg, csr, h16, dis, b2, agg, stats + ST2, N);

    // ================= Layer 3: 64 -> 32 =================
    k_mma_gemm<32><<<ngemm, 256>>>(agg, whi + W3_OFF, h16, dis, N, 64,
                                   stats + ST2, g2, bt2);
    k_gather16<32><<<cdiv((long long)N * 4, 256), 256>>>(
        rowptr, deg, csr, h16, dis, b3, agg, stats + ST3, N);

    // ================= Final FC: 32 -> 1 (in-kernel BN + ReLU) =================
    k_final_fc<<<cdiv((long long)N * 32, 256), 256>>>(agg, stats + ST3, g3, bt3,
                                                      Wfc, bfc, out, N);
}

// round 10
// speedup vs baseline: 3.2604x; 1.0688x over previous
#include <cuda_runtime.h>
#include <cuda_fp16.h>
#include <cuda_bf16.h>
#include <cstdint>

#define MAXN 100000
#define MAXE 3200000
#define MAXF 128

#define W2_OFF (256 * 128)
#define W3_OFF (256 * 128 + 128 * 64)
#define WTOT   (256 * 128 + 128 * 64 + 64 * 32)

// stats regions: [0,256) layer1 (F=128), [256,384) layer2 (F=64), [384,448) layer3 (F=32)
#define ST2 256
#define ST3 384
#define STTOT 448

// Scratch (device globals; no cudaMalloc allowed)
__device__ float  g_agg[(size_t)MAXN * MAXF];
__device__ __half g_h16[(size_t)MAXN * MAXF];
__device__ float  g_dis[MAXN];
__device__ int    g_deg[MAXN];
__device__ int    g_rowptr[MAXN + 1];
__device__ int    g_cursor[MAXN + 1];
__device__ int    g_bsum[256];
__device__ int    g_csr_src[MAXE];
__device__ float  g_stats[STTOT];
__device__ __half g_whi[WTOT];

// ---------------------------------------------------------------------------
// Prologue 1: fused degree count + weight fp16 round/transpose
// ---------------------------------------------------------------------------
__global__ void k_pro1(const int* __restrict__ ei, int* __restrict__ deg, int E, int nsc,
                       const float* __restrict__ W1, const float* __restrict__ W2,
                       const float* __restrict__ W3, __half* __restrict__ Wh)
{
    if ((int)blockIdx.x < nsc) {
        int e = blockIdx.x * 256 + threadIdx.x;
        if (e < E) atomicAdd(&deg[__ldg(ei + E + e)], 1);
        return;
    }
    int i = (blockIdx.x - nsc) * 256 + threadIdx.x;
    const float* W;
    int K, Nn, off, li;
    if (i < W2_OFF)       { W = W1; K = 256; Nn = 128; off = 0;      li = i; }
    else if (i < W3_OFF)  { W = W2; K = 128; Nn = 64;  off = W2_OFF; li = i - W2_OFF; }
    else if (i < WTOT)    { W = W3; K = 64;  Nn = 32;  off = W3_OFF; li = i - W3_OFF; }
    else return;
    int n = li / K, k = li - n * K;
    Wh[off + li] = __float2half_rn(__ldg(W + (size_t)k * Nn + n));
}

// ---------------------------------------------------------------------------
// Scan (exclusive) of deg -> rowptr; also emits dis = rsqrt(deg+1)
// ---------------------------------------------------------------------------
__global__ void k_scan_block(const int* __restrict__ deg, int* __restrict__ exc,
                             int* __restrict__ bsum, float* __restrict__ dis, int N)
{
    __shared__ int sh[1024];
    int i = blockIdx.x * 1024 + threadIdx.x;
    int v = (i < N) ? deg[i] : 0;
    sh[threadIdx.x] = v;
    __syncthreads();
#pragma unroll
    for (int o = 1; o < 1024; o <<= 1) {
        int t = (threadIdx.x >= o) ? sh[threadIdx.x - o] : 0;
        __syncthreads();
        sh[threadIdx.x] += t;
        __syncthreads();
    }
    if (i < N) {
        exc[i] = sh[threadIdx.x] - v;
        dis[i] = rsqrtf((float)v + 1.0f);
    }
    if (threadIdx.x == 1023) bsum[blockIdx.x] = sh[1023];
}

// Adds block offsets (bsum scanned redundantly per block in smem),
// mirrors rowptr->cursor, zeroes ALL BN stats regions.
__global__ void k_scan_add2(int* __restrict__ rowptr, int* __restrict__ cursor,
                            const int* __restrict__ bsum, float* __restrict__ stats,
                            int nb, int N)
{
    __shared__ int sh[256];
    __shared__ int sexc[256];
    int t = threadIdx.x;
    int v = (t < nb) ? __ldg(bsum + t) : 0;
    sh[t] = v;
    __syncthreads();
#pragma unroll
    for (int o = 1; o < 256; o <<= 1) {
        int u = (t >= o) ? sh[t - o] : 0;
        __syncthreads();
        sh[t] += u;
        __syncthreads();
    }
    sexc[t] = sh[t] - v;   // exclusive prefix of bsum
    __syncthreads();

    int i = blockIdx.x * 256 + t;
    if (i < N) {
        int val = rowptr[i] + sexc[i >> 10];
        rowptr[i] = val;
        cursor[i] = val;
    }
    if (blockIdx.x == 0) {
        for (int f = t; f < STTOT; f += 256) stats[f] = 0.0f;
    }
}

// ---------------------------------------------------------------------------
// 2-product split GEMM core, SOFTWARE-PIPELINED A loads:
//   C16[M,BN] = half( dis[m] * (BNReLU?(A[M,K]) @ W16[K,BN]) )
// A split in-register to hi+lo fp16 (exact to 2^-22); W fp16-rounded.
// Products: AhiWhi + AloWhi.  BN scale/shift computed in-kernel from stats.
// BM=64, BK=32, 256 threads (8 warps as 2x4), warp tile 32 x (BN/4).
// Next A tile is prefetched into registers during the current tile's MMAs,
// keeping DRAM loads in flight through the compute phase.
// ---------------------------------------------------------------------------
__device__ __forceinline__ void mma16816(float* c, const uint32_t* a, const uint32_t* b)
{
    asm volatile(
        "mma.sync.aligned.m16n8k16.row.col.f32.f16.f16.f32 "
        "{%0,%1,%2,%3}, {%4,%5,%6,%7}, {%8,%9}, {%0,%1,%2,%3};"
        : "+f"(c[0]), "+f"(c[1]), "+f"(c[2]), "+f"(c[3])
        : "r"(a[0]), "r"(a[1]), "r"(a[2]), "r"(a[3]), "r"(b[0]), "r"(b[1]));
}

template <int BN>
__device__ __forceinline__ void gemm_body(
    int bid, const float* __restrict__ A, const __half* __restrict__ Wh,
    __half* __restrict__ C16, const float* __restrict__ disv, int M, int K,
    const float* __restrict__ stats, const float* __restrict__ gam,
    const float* __restrict__ bt)
{
    constexpr int BM = 64, BK = 32;
    constexpr int LDA = BK + 8;           // halfs; 80B row stride
    constexpr int MT = 2;
    constexpr int NT = BN / 32;
    constexpr int WNW = BN / 4;

    __shared__ __align__(16) __half Ah[BM][LDA];
    __shared__ __align__(16) __half Al[BM][LDA];
    __shared__ __align__(16) __half Bh[BN][LDA];
    __shared__ __align__(16) float bnp_s[512];   // [K] scale | [K] shift

    const int tid  = threadIdx.x;
    const int warp = tid >> 5;
    const int lane = tid & 31;
    const int g    = lane >> 2;
    const int t4   = lane & 3;
    const int wmi  = warp & 1;
    const int wni  = warp >> 1;
    const int m0   = bid * BM;
    const bool has_bn = (stats != nullptr);

    if (has_bn) {
        float inv_n = 1.0f / (float)M;
        for (int f = tid; f < K; f += 256) {
            float mu  = stats[f] * inv_n;
            float var = fmaxf(stats[K + f] * inv_n - mu * mu, 0.0f);
            float sc  = gam[f] * rsqrtf(var + 1e-5f);
            bnp_s[f]     = sc;
            bnp_s[K + f] = bt[f] - mu * sc;
        }
    }
    __syncthreads();

    // A staging coordinates: 64x32 floats = 512 float4, 2 per thread
    const int a_row0 = tid >> 3;              // idx = tid       -> rows 0..31
    const int a_row1 = (tid + 256) >> 3;      // idx = tid + 256 -> rows 32..63
    const int a_c4   = tid & 7;

    auto ldA = [&](int k0, float4* r) {
        int gr0 = m0 + a_row0;
        int gr1 = m0 + a_row1;
        r[0] = (gr0 < M) ? *(const float4*)(A + (size_t)gr0 * K + k0 + a_c4 * 4)
                         : make_float4(0.f, 0.f, 0.f, 0.f);
        r[1] = (gr1 < M) ? *(const float4*)(A + (size_t)gr1 * K + k0 + a_c4 * 4)
                         : make_float4(0.f, 0.f, 0.f, 0.f);
    };

    auto stA = [&](float4* r, int k0) {
#pragma unroll
        for (int i = 0; i < 2; i++) {
            int row = (i == 0) ? a_row0 : a_row1;
            float4 v = r[i];
            if (has_bn) {
                int kidx = k0 + a_c4 * 4;
                float4 sc = *(const float4*)&bnp_s[kidx];
                float4 sh = *(const float4*)&bnp_s[K + kidx];
                v.x = fmaxf(fmaf(v.x, sc.x, sh.x), 0.f);
                v.y = fmaxf(fmaf(v.y, sc.y, sh.y), 0.f);
                v.z = fmaxf(fmaf(v.z, sc.z, sh.z), 0.f);
                v.w = fmaxf(fmaf(v.w, sc.w, sh.w), 0.f);
            }
            float f[4] = {v.x, v.y, v.z, v.w};
            __half h[4], l[4];
#pragma unroll
            for (int q = 0; q < 4; q++) {
                h[q] = __float2half_rn(f[q]);
                l[q] = __float2half_rn(f[q] - __half2float(h[q]));
            }
            uint2 uh, ul;
            ((__half2*)&uh)[0] = __halves2half2(h[0], h[1]);
            ((__half2*)&uh)[1] = __halves2half2(h[2], h[3]);
            ((__half2*)&ul)[0] = __halves2half2(l[0], l[1]);
            ((__half2*)&ul)[1] = __halves2half2(l[2], l[3]);
            *(uint2*)&Ah[row][a_c4 * 4] = uh;
            *(uint2*)&Al[row][a_c4 * 4] = ul;
        }
    };

    float acc[MT][NT][4];
#pragma unroll
    for (int mt = 0; mt < MT; mt++)
#pragma unroll
        for (int nt = 0; nt < NT; nt++)
#pragma unroll
            for (int q = 0; q < 4; q++) acc[mt][nt][q] = 0.0f;

    float4 cur[2];
    ldA(0, cur);

    for (int k0 = 0; k0 < K; k0 += BK) {
        stA(cur, k0);
        // ---- stage B tile (fp16, transposed [BN][K]; L2-resident) ----
#pragma unroll
        for (int i = 0; i < (BN * 4 + 255) / 256; i++) {
            int idx = tid + i * 256;
            if (idx < BN * 4) {
                int n  = idx >> 2;
                int c8 = idx & 3;
                *(uint4*)&Bh[n][c8 * 8] = *(const uint4*)(Wh + (size_t)n * K + k0 + c8 * 8);
            }
        }
        __syncthreads();

        // ---- prefetch next A tile into registers (LDGs overlap compute) ----
        float4 nxt[2];
        if (k0 + BK < K) ldA(k0 + BK, nxt);
        else { nxt[0] = make_float4(0.f,0.f,0.f,0.f); nxt[1] = nxt[0]; }

#pragma unroll
        for (int kk = 0; kk < BK; kk += 16) {
            uint32_t ah[MT][4], al[MT][4], bh[NT][2];
#pragma unroll
            for (int mt = 0; mt < MT; mt++) {
                int r = wmi * 32 + mt * 16 + g;
                ah[mt][0] = *(const uint32_t*)&Ah[r][kk + t4 * 2];
                ah[mt][1] = *(const uint32_t*)&Ah[r + 8][kk + t4 * 2];
                ah[mt][2] = *(const uint32_t*)&Ah[r][kk + t4 * 2 + 8];
                ah[mt][3] = *(const uint32_t*)&Ah[r + 8][kk + t4 * 2 + 8];
                al[mt][0] = *(const uint32_t*)&Al[r][kk + t4 * 2];
                al[mt][1] = *(const uint32_t*)&Al[r + 8][kk + t4 * 2];
                al[mt][2] = *(const uint32_t*)&Al[r][kk + t4 * 2 + 8];
                al[mt][3] = *(const uint32_t*)&Al[r + 8][kk + t4 * 2 + 8];
            }
#pragma unroll
            for (int nt = 0; nt < NT; nt++) {
                int n = wni * WNW + nt * 8 + g;
                bh[nt][0] = *(const uint32_t*)&Bh[n][kk + t4 * 2];
                bh[nt][1] = *(const uint32_t*)&Bh[n][kk + t4 * 2 + 8];
            }
#pragma unroll
            for (int mt = 0; mt < MT; mt++)
#pragma unroll
                for (int nt = 0; nt < NT; nt++) {
                    mma16816(acc[mt][nt], ah[mt], bh[nt]);
                    mma16816(acc[mt][nt], al[mt], bh[nt]);
                }
        }
        __syncthreads();
        cur[0] = nxt[0];
        cur[1] = nxt[1];
    }

    // ---- epilogue: scale by dis, convert to fp16, store ----
#pragma unroll
    for (int mt = 0; mt < MT; mt++) {
#pragma unroll
        for (int nt = 0; nt < NT; nt++) {
            int r0 = m0 + wmi * 32 + mt * 16 + g;
            int r1 = r0 + 8;
            int c  = wni * WNW + nt * 8 + t4 * 2;
            if (r0 < M) {
                float d = __ldg(disv + r0);
                *(__half2*)&C16[(size_t)r0 * BN + c] =
                    __floats2half2_rn(acc[mt][nt][0] * d, acc[mt][nt][1] * d);
            }
            if (r1 < M) {
                float d = __ldg(disv + r1);
                *(__half2*)&C16[(size_t)r1 * BN + c] =
                    __floats2half2_rn(acc[mt][nt][2] * d, acc[mt][nt][3] * d);
            }
        }
    }
}

template <int BN>
__global__ __launch_bounds__(256) void k_mma_gemm(
    const float* __restrict__ A, const __half* __restrict__ Wh,
    __half* __restrict__ C16, const float* __restrict__ disv, int M, int K,
    const float* __restrict__ stats, const float* __restrict__ gam,
    const float* __restrict__ bt)
{
    gemm_body<BN>(blockIdx.x, A, Wh, C16, disv, M, K, stats, gam, bt);
}

// Fused CSR scatter + layer-1 GEMM (independent work, interleaved block stripe)
__global__ __launch_bounds__(256) void k_scatter_gemm1(
    const int* __restrict__ ei, int* __restrict__ cursor, int* __restrict__ csr_src,
    int E, int ngemm,
    const float* __restrict__ A, const __half* __restrict__ Wh,
    __half* __restrict__ C16, const float* __restrict__ disv, int M)
{
    int b = blockIdx.x;
    bool is_gemm;
    int id;
    if (b < 2 * ngemm) { is_gemm = (b & 1); id = b >> 1; }
    else               { is_gemm = false;   id = b - ngemm; }
    if (!is_gemm) {
        int e = id * 256 + threadIdx.x;
        if (e < E) {
            int src = __ldg(ei + e);
            int dst = __ldg(ei + E + e);
            int pos = atomicAdd(&cursor[dst], 1);
            csr_src[pos] = src;
        }
        return;
    }
    gemm_body<128>(id, A, Wh, C16, disv, M, 256, nullptr, nullptr, nullptr);
}

// ---------------------------------------------------------------------------
// CSR gather on fp16 prescaled rows + fused BN statistics (4-edge unroll)
// ---------------------------------------------------------------------------
template <int F>
__global__ __launch_bounds__(256) void k_gather16(
    const int* __restrict__ rowptr, const int* __restrict__ deg,
    const int* __restrict__ csr_src, const __half* __restrict__ h16,
    const float* __restrict__ dis, const float* __restrict__ bias,
    float* __restrict__ agg, float* __restrict__ stats, int N)
{
    constexpr int G = F / 8;
    __shared__ float ssum[F];
    __shared__ float ssq[F];
    const int tid = threadIdx.x;
    if (tid < F) { ssum[tid] = 0.0f; ssq[tid] = 0.0f; }
    __syncthreads();

    int t    = blockIdx.x * 256 + tid;
    int node = t / G;
    int j    = t - node * G;
    const bool valid = node < N;
    const int cn = valid ? node : 0;

    int start = __ldg(rowptr + cn);
    int cnt   = valid ? __ldg(deg + cn) : 0;
    const __half* base = h16 + j * 8;

    float a[8];
#pragma unroll
    for (int q = 0; q < 8; q++) a[q] = 0.0f;

    auto addv = [&](uint4 v) {
        const __half2* hv = (const __half2*)&v;
#pragma unroll
        for (int q = 0; q < 4; q++) {
            float2 f = __half22float2(hv[q]);
            a[2 * q]     += f.x;
            a[2 * q + 1] += f.y;
        }
    };

    int p = 0;
    for (; p + 4 <= cnt; p += 4) {
        int s0 = __ldg(csr_src + start + p);
        int s1 = __ldg(csr_src + start + p + 1);
        int s2 = __ldg(csr_src + start + p + 2);
        int s3 = __ldg(csr_src + start + p + 3);
        uint4 v0 = __ldg((const uint4*)(base + (size_t)s0 * F));
        uint4 v1 = __ldg((const uint4*)(base + (size_t)s1 * F));
        uint4 v2 = __ldg((const uint4*)(base + (size_t)s2 * F));
        uint4 v3 = __ldg((const uint4*)(base + (size_t)s3 * F));
        addv(v0); addv(v1); addv(v2); addv(v3);
    }
    for (; p < cnt; p++) {
        int s = __ldg(csr_src + start + p);
        addv(__ldg((const uint4*)(base + (size_t)s * F)));
    }
    if (valid) addv(__ldg((const uint4*)(base + (size_t)cn * F)));  // self-loop

    float d = valid ? __ldg(dis + cn) : 0.0f;
    float4 b0 = __ldg((const float4*)(bias + j * 8));
    float4 b1 = __ldg((const float4*)(bias + j * 8) + 1);
    float r[8];
    r[0] = fmaf(d, a[0], b0.x); r[1] = fmaf(d, a[1], b0.y);
    r[2] = fmaf(d, a[2], b0.z); r[3] = fmaf(d, a[3], b0.w);
    r[4] = fmaf(d, a[4], b1.x); r[5] = fmaf(d, a[5], b1.y);
    r[6] = fmaf(d, a[6], b1.z); r[7] = fmaf(d, a[7], b1.w);

    if (valid) {
        float4* o = (float4*)(agg + (size_t)node * F + j * 8);
        o[0] = make_float4(r[0], r[1], r[2], r[3]);
        o[1] = make_float4(r[4], r[5], r[6], r[7]);
    } else {
#pragma unroll
        for (int q = 0; q < 8; q++) r[q] = 0.0f;
    }

    float s2v[8];
#pragma unroll
    for (int q = 0; q < 8; q++) s2v[q] = r[q] * r[q];
#pragma unroll
    for (int o = 16; o >= G; o >>= 1) {
#pragma unroll
        for (int q = 0; q < 8; q++) {
            r[q]   += __shfl_xor_sync(0xFFFFFFFFu, r[q],   o);
            s2v[q] += __shfl_xor_sync(0xFFFFFFFFu, s2v[q], o);
        }
    }
    int lane = tid & 31;
    if (lane < G) {
#pragma unroll
        for (int q = 0; q < 8; q++) {
            atomicAdd(&ssum[lane * 8 + q], r[q]);
            atomicAdd(&ssq[lane * 8 + q],  s2v[q]);
        }
    }
    __syncthreads();
    if (tid < F) {
        atomicAdd(&stats[tid],     ssum[tid]);
        atomicAdd(&stats[F + tid], ssq[tid]);
    }
}

// ---------------------------------------------------------------------------
// Final FC with in-kernel BN finalize + fused BN+ReLU
// ---------------------------------------------------------------------------
__global__ void k_final_fc(const float* __restrict__ h, const float* __restrict__ stats,
                           const float* __restrict__ gam, const float* __restrict__ bt,
                           const float* __restrict__ W, const float* __restrict__ b,
                           float* __restrict__ out, int N)
{
    __shared__ float sc_s[32], sh_s[32];
    int tid = threadIdx.x;
    if (tid < 32) {
        float inv_n = 1.0f / (float)N;
        float mu  = stats[tid] * inv_n;
        float var = fmaxf(stats[32 + tid] * inv_n - mu * mu, 0.0f);
        float sc  = gam[tid] * rsqrtf(var + 1e-5f);
        sc_s[tid] = sc;
        sh_s[tid] = bt[tid] - mu * sc;
    }
    __syncthreads();
    int lane = tid & 31;
    int node = (blockIdx.x * blockDim.x + tid) >> 5;
    if (node >= N) return;
    float v = fmaxf(fmaf(h[(size_t)node * 32 + lane], sc_s[lane], sh_s[lane]), 0.0f)
              * __ldg(W + lane);
#pragma unroll
    for (int o = 16; o; o >>= 1) v += __shfl_down_sync(0xFFFFFFFFu, v, o);
    if (lane == 0) out[node] = v + __ldg(b);
}

// ---------------------------------------------------------------------------
static inline int cdiv(long long a, long long b) { return (int)((a + b - 1) / b); }

extern "C" void kernel_launch(void* const* d_in, const int* in_sizes, int n_in,
                              void* d_out, int out_size)
{
    const float* x   = (const float*)d_in[0];
    const int*   ei  = (const int*)d_in[1];
    const float* W1  = (const float*)d_in[2];
    const float* b1  = (const float*)d_in[3];
    const float* g1  = (const float*)d_in[4];
    const float* bt1 = (const float*)d_in[5];
    const float* W2  = (const float*)d_in[6];
    const float* b2  = (const float*)d_in[7];
    const float* g2  = (const float*)d_in[8];
    const float* bt2 = (const float*)d_in[9];
    const float* W3  = (const float*)d_in[10];
    const float* b3  = (const float*)d_in[11];
    const float* g3  = (const float*)d_in[12];
    const float* bt3 = (const float*)d_in[13];
    const float* Wfc = (const float*)d_in[14];
    const float* bfc = (const float*)d_in[15];
    float* out = (float*)d_out;

    const int N = in_sizes[0] / 256;
    const int E = in_sizes[1] / 2;

    float *agg, *dis, *stats;
    __half *h16, *whi;
    int *deg, *rowptr, *cursor, *bsum, *csr;
    cudaGetSymbolAddress((void**)&agg,    g_agg);
    cudaGetSymbolAddress((void**)&h16,    g_h16);
    cudaGetSymbolAddress((void**)&dis,    g_dis);
    cudaGetSymbolAddress((void**)&deg,    g_deg);
    cudaGetSymbolAddress((void**)&rowptr, g_rowptr);
    cudaGetSymbolAddress((void**)&cursor, g_cursor);
    cudaGetSymbolAddress((void**)&bsum,   g_bsum);
    cudaGetSymbolAddress((void**)&csr,    g_csr_src);
    cudaGetSymbolAddress((void**)&stats,  g_stats);
    cudaGetSymbolAddress((void**)&whi,    g_whi);

    const int nsc   = cdiv(E, 256);
    const int nw    = cdiv(WTOT, 256);
    const int nb    = cdiv(N, 1024);
    const int ngemm = cdiv(N, 64);

    // ---- prologue: degree count + weight round, scan(+dis), scatter+GEMM1 ----
    cudaMemsetAsync(deg, 0, (size_t)N * sizeof(int));
    k_pro1<<<nsc + nw, 256>>>(ei, deg, E, nsc, W1, W2, W3, whi);
    k_scan_block<<<nb, 1024>>>(deg, rowptr, bsum, dis, N);
    k_scan_add2<<<cdiv(N, 256), 256>>>(rowptr, cursor, bsum, stats, nb, N);
    k_scatter_gemm1<<<ngemm + nsc, 256>>>(ei, cursor, csr, E, ngemm,
                                          x, whi, h16, dis, N);

    // ================= Layer 1 gather (F=128) =================
    k_gather16<128><<<cdiv((long long)N * 16, 256), 256>>>(
        rowptr, deg, csr, h16, dis, b1, agg, stats, N);

    // ================= Layer 2: 128 -> 64 =================
    k_mma_gemm<64><<<ngemm, 256>>>(agg, whi + W2_OFF, h16, dis, N, 128,
                                   stats, g1, bt1);
    k_gather16<64><<<cdiv((long long)N * 8, 256), 256>>>(
        rowptr, deg, csr, h16, dis, b2, agg, stats + ST2, N);

    // ================= Layer 3: 64 -> 32 =================
    k_mma_gemm<32><<<ngemm, 256>>>(agg, whi + W3_OFF, h16, dis, N, 64,
                                   stats + ST2, g2, bt2);
    k_gather16<32><<<cdiv((long long)N * 4, 256), 256>>>(
        rowptr, deg, csr, h16, dis, b3, agg, stats + ST3, N);

    // ================= Final FC: 32 -> 1 (in-kernel BN + ReLU) =================
    k_final_fc<<<cdiv((long long)N * 32, 256), 256>>>(agg, stats + ST3, g3, bt3,
                                                      Wfc, bfc, out, N);
}

// round 12
// speedup vs baseline: 3.2772x; 1.0052x over previous
#include <cuda_runtime.h>
#include <cuda_fp16.h>
#include <cuda_bf16.h>
#include <cstdint>

#define MAXN 100000
#define MAXE 3200000
#define MAXF 128

#define W2_OFF (256 * 128)
#define W3_OFF (256 * 128 + 128 * 64)
#define WTOT   (256 * 128 + 128 * 64 + 64 * 32)

// stats regions: [0,256) layer1 (F=128), [256,384) layer2 (F=64), [384,448) layer3 (F=32)
#define ST2 256
#define ST3 384
#define STTOT 448

// Scratch (device globals; no cudaMalloc allowed)
__device__ float  g_agg[(size_t)MAXN * MAXF];        // fp32 aggregation output
__device__ __half g_h16[(size_t)MAXN * MAXF];        // fp16 dis-prescaled features
__device__ float  g_dis[MAXN];
__device__ int    g_deg[MAXN];
__device__ int    g_rowptr[MAXN + 1];
__device__ int    g_cursor[MAXN + 1];
__device__ int    g_bsum[256];
__device__ int    g_csr_src[MAXE];
__device__ float  g_stats[STTOT];
__device__ __half g_whi[WTOT];

// ---------------------------------------------------------------------------
// Prologue 1: fused degree count + weight fp16 round/transpose
// ---------------------------------------------------------------------------
__global__ void k_pro1(const int* __restrict__ ei, int* __restrict__ deg, int E, int nsc,
                       const float* __restrict__ W1, const float* __restrict__ W2,
                       const float* __restrict__ W3, __half* __restrict__ Wh)
{
    if ((int)blockIdx.x < nsc) {
        int e = blockIdx.x * 256 + threadIdx.x;
        if (e < E) atomicAdd(&deg[__ldg(ei + E + e)], 1);
        return;
    }
    int i = (blockIdx.x - nsc) * 256 + threadIdx.x;
    const float* W;
    int K, Nn, off, li;
    if (i < W2_OFF)       { W = W1; K = 256; Nn = 128; off = 0;      li = i; }
    else if (i < W3_OFF)  { W = W2; K = 128; Nn = 64;  off = W2_OFF; li = i - W2_OFF; }
    else if (i < WTOT)    { W = W3; K = 64;  Nn = 32;  off = W3_OFF; li = i - W3_OFF; }
    else return;
    int n = li / K, k = li - n * K;
    Wh[off + li] = __float2half_rn(__ldg(W + (size_t)k * Nn + n));
}

// ---------------------------------------------------------------------------
// Scan (exclusive) of deg -> rowptr; also emits dis = rsqrt(deg+1)
// ---------------------------------------------------------------------------
__global__ void k_scan_block(const int* __restrict__ deg, int* __restrict__ exc,
                             int* __restrict__ bsum, float* __restrict__ dis, int N)
{
    __shared__ int sh[1024];
    int i = blockIdx.x * 1024 + threadIdx.x;
    int v = (i < N) ? deg[i] : 0;
    sh[threadIdx.x] = v;
    __syncthreads();
#pragma unroll
    for (int o = 1; o < 1024; o <<= 1) {
        int t = (threadIdx.x >= o) ? sh[threadIdx.x - o] : 0;
        __syncthreads();
        sh[threadIdx.x] += t;
        __syncthreads();
    }
    if (i < N) {
        exc[i] = sh[threadIdx.x] - v;
        dis[i] = rsqrtf((float)v + 1.0f);
    }
    if (threadIdx.x == 1023) bsum[blockIdx.x] = sh[1023];
}

// Adds block offsets (bsum scanned redundantly per block in smem),
// mirrors rowptr->cursor, zeroes ALL BN stats regions.
__global__ void k_scan_add2(int* __restrict__ rowptr, int* __restrict__ cursor,
                            const int* __restrict__ bsum, float* __restrict__ stats,
                            int nb, int N)
{
    __shared__ int sh[256];
    __shared__ int sexc[256];
    int t = threadIdx.x;
    int v = (t < nb) ? __ldg(bsum + t) : 0;
    sh[t] = v;
    __syncthreads();
#pragma unroll
    for (int o = 1; o < 256; o <<= 1) {
        int u = (t >= o) ? sh[t - o] : 0;
        __syncthreads();
        sh[t] += u;
        __syncthreads();
    }
    sexc[t] = sh[t] - v;   // exclusive prefix of bsum
    __syncthreads();

    int i = blockIdx.x * 256 + t;
    if (i < N) {
        int val = rowptr[i] + sexc[i >> 10];
        rowptr[i] = val;
        cursor[i] = val;
    }
    if (blockIdx.x == 0) {
        for (int f = t; f < STTOT; f += 256) stats[f] = 0.0f;
    }
}

// ---------------------------------------------------------------------------
// MMA + ldmatrix helpers
// ---------------------------------------------------------------------------
__device__ __forceinline__ void mma16816(float* c, const uint32_t* a, const uint32_t* b)
{
    asm volatile(
        "mma.sync.aligned.m16n8k16.row.col.f32.f16.f16.f32 "
        "{%0,%1,%2,%3}, {%4,%5,%6,%7}, {%8,%9}, {%0,%1,%2,%3};"
        : "+f"(c[0]), "+f"(c[1]), "+f"(c[2]), "+f"(c[3])
        : "r"(a[0]), "r"(a[1]), "r"(a[2]), "r"(a[3]), "r"(b[0]), "r"(b[1]));
}
__device__ __forceinline__ void ldsm_x4(uint32_t* r, uint32_t addr)
{
    asm volatile("ldmatrix.sync.aligned.m8n8.x4.shared.b16 {%0,%1,%2,%3}, [%4];"
                 : "=r"(r[0]), "=r"(r[1]), "=r"(r[2]), "=r"(r[3]) : "r"(addr));
}
__device__ __forceinline__ void ldsm_x2(uint32_t* r, uint32_t addr)
{
    asm volatile("ldmatrix.sync.aligned.m8n8.x2.shared.b16 {%0,%1}, [%2];"
                 : "=r"(r[0]), "=r"(r[1]) : "r"(addr));
}

// ---------------------------------------------------------------------------
// 2-product split GEMM core (A fp32, hi/lo split; W fp16-rounded),
// ldmatrix fragment loads, register-pipelined A global loads:
//   C16[M,BN] = half( dis[m] * (BNReLU?(A[M,K]) @ W16[K,BN]) )
// BN scale/shift computed in-kernel from raw stats (if stats != nullptr).
// BM=64, BK=32, 256 threads (8 warps 2x4), warp tile 32 x (BN/4).
// ---------------------------------------------------------------------------
template <int BN>
__device__ __forceinline__ void gemm_body(
    int bid, const float* __restrict__ A, const __half* __restrict__ Wh,
    __half* __restrict__ C16, const float* __restrict__ disv, int M, int K,
    const float* __restrict__ stats, const float* __restrict__ gam,
    const float* __restrict__ bt)
{
    constexpr int BM = 64, BK = 32;
    constexpr int LDA = BK + 8;           // halfs; 80B row stride
    constexpr int MT = 2;
    constexpr int NT = BN / 32;
    constexpr int WNW = BN / 4;

    __shared__ __align__(16) __half Ah[BM][LDA];
    __shared__ __align__(16) __half Al[BM][LDA];
    __shared__ __align__(16) __half Bh[BN][LDA];
    __shared__ __align__(16) float bnp_s[512];   // [K] scale | [K] shift

    const int tid  = threadIdx.x;
    const int warp = tid >> 5;
    const int lane = tid & 31;
    const int g    = lane >> 2;
    const int t4   = lane & 3;
    const int wmi  = warp & 1;
    const int wni  = warp >> 1;
    const int m0   = bid * BM;
    const bool has_bn = (stats != nullptr);

    const uint32_t ah_base = (uint32_t)__cvta_generic_to_shared(&Ah[0][0]);
    const uint32_t al_base = (uint32_t)__cvta_generic_to_shared(&Al[0][0]);
    const uint32_t bh_base = (uint32_t)__cvta_generic_to_shared(&Bh[0][0]);
    const int arow = lane & 15;
    const int acol = (lane & 16) ? 8 : 0;
    const int brow = lane & 7;
    const int bcol = (lane & 8) ? 8 : 0;

    if (has_bn) {
        float inv_n = 1.0f / (float)M;
        for (int f = tid; f < K; f += 256) {
            float mu  = stats[f] * inv_n;
            float var = fmaxf(stats[K + f] * inv_n - mu * mu, 0.0f);
            float sc  = gam[f] * rsqrtf(var + 1e-5f);
            bnp_s[f]     = sc;
            bnp_s[K + f] = bt[f] - mu * sc;
        }
    }
    __syncthreads();

    // A staging: 64x32 floats = 512 float4, 2 per thread
    const int a_row0 = tid >> 3;
    const int a_row1 = (tid + 256) >> 3;
    const int a_c4   = tid & 7;

    auto ldA = [&](int k0, float4* r) {
        int gr0 = m0 + a_row0;
        int gr1 = m0 + a_row1;
        r[0] = (gr0 < M) ? *(const float4*)(A + (size_t)gr0 * K + k0 + a_c4 * 4)
                         : make_float4(0.f, 0.f, 0.f, 0.f);
        r[1] = (gr1 < M) ? *(const float4*)(A + (size_t)gr1 * K + k0 + a_c4 * 4)
                         : make_float4(0.f, 0.f, 0.f, 0.f);
    };

    auto stA = [&](float4* r, int k0) {
#pragma unroll
        for (int i = 0; i < 2; i++) {
            int row = (i == 0) ? a_row0 : a_row1;
            float4 v = r[i];
            if (has_bn) {
                int kidx = k0 + a_c4 * 4;
                float4 sc = *(const float4*)&bnp_s[kidx];
                float4 sh = *(const float4*)&bnp_s[K + kidx];
                v.x = fmaxf(fmaf(v.x, sc.x, sh.x), 0.f);
                v.y = fmaxf(fmaf(v.y, sc.y, sh.y), 0.f);
                v.z = fmaxf(fmaf(v.z, sc.z, sh.z), 0.f);
                v.w = fmaxf(fmaf(v.w, sc.w, sh.w), 0.f);
            }
            float f[4] = {v.x, v.y, v.z, v.w};
            __half h[4], l[4];
#pragma unroll
            for (int q = 0; q < 4; q++) {
                h[q] = __float2half_rn(f[q]);
                l[q] = __float2half_rn(f[q] - __half2float(h[q]));
            }
            uint2 uh, ul;
            ((__half2*)&uh)[0] = __halves2half2(h[0], h[1]);
            ((__half2*)&uh)[1] = __halves2half2(h[2], h[3]);
            ((__half2*)&ul)[0] = __halves2half2(l[0], l[1]);
            ((__half2*)&ul)[1] = __halves2half2(l[2], l[3]);
            *(uint2*)&Ah[row][a_c4 * 4] = uh;
            *(uint2*)&Al[row][a_c4 * 4] = ul;
        }
    };

    float acc[MT][NT][4];
#pragma unroll
    for (int mt = 0; mt < MT; mt++)
#pragma unroll
        for (int nt = 0; nt < NT; nt++)
#pragma unroll
            for (int q = 0; q < 4; q++) acc[mt][nt][q] = 0.0f;

    float4 cur[2];
    ldA(0, cur);

    for (int k0 = 0; k0 < K; k0 += BK) {
        stA(cur, k0);
        // ---- stage B tile (fp16, transposed [BN][K]; L2-resident) ----
#pragma unroll
        for (int i = 0; i < (BN * 4 + 255) / 256; i++) {
            int idx = tid + i * 256;
            if (idx < BN * 4) {
                int n  = idx >> 2;
                int c8 = idx & 3;
                *(uint4*)&Bh[n][c8 * 8] = *(const uint4*)(Wh + (size_t)n * K + k0 + c8 * 8);
            }
        }
        __syncthreads();

        // ---- prefetch next A tile into registers (LDGs overlap compute) ----
        float4 nxt[2];
        if (k0 + BK < K) ldA(k0 + BK, nxt);
        else { nxt[0] = make_float4(0.f,0.f,0.f,0.f); nxt[1] = nxt[0]; }

#pragma unroll
        for (int kk = 0; kk < BK; kk += 16) {
            uint32_t ah[MT][4], al[MT][4], bh[NT][2];
#pragma unroll
            for (int mt = 0; mt < MT; mt++) {
                uint32_t off = ((wmi * 32 + mt * 16 + arow) * LDA + kk + acol) * 2;
                ldsm_x4(ah[mt], ah_base + off);
                ldsm_x4(al[mt], al_base + off);
            }
#pragma unroll
            for (int nt = 0; nt < NT; nt++) {
                uint32_t off = ((wni * WNW + nt * 8 + brow) * LDA + kk + bcol) * 2;
                ldsm_x2(bh[nt], bh_base + off);
            }
#pragma unroll
            for (int mt = 0; mt < MT; mt++)
#pragma unroll
                for (int nt = 0; nt < NT; nt++) {
                    mma16816(acc[mt][nt], ah[mt], bh[nt]);
                    mma16816(acc[mt][nt], al[mt], bh[nt]);
                }
        }
        __syncthreads();
        cur[0] = nxt[0];
        cur[1] = nxt[1];
    }

    // ---- epilogue: scale by dis, convert to fp16, store ----
#pragma unroll
    for (int mt = 0; mt < MT; mt++) {
#pragma unroll
        for (int nt = 0; nt < NT; nt++) {
            int r0 = m0 + wmi * 32 + mt * 16 + g;
            int r1 = r0 + 8;
            int c  = wni * WNW + nt * 8 + t4 * 2;
            if (r0 < M) {
                float d = __ldg(disv + r0);
                *(__half2*)&C16[(size_t)r0 * BN + c] =
                    __floats2half2_rn(acc[mt][nt][0] * d, acc[mt][nt][1] * d);
            }
            if (r1 < M) {
                float d = __ldg(disv + r1);
                *(__half2*)&C16[(size_t)r1 * BN + c] =
                    __floats2half2_rn(acc[mt][nt][2] * d, acc[mt][nt][3] * d);
            }
        }
    }
}

template <int BN>
__global__ __launch_bounds__(256) void k_mma_gemm(
    const float* __restrict__ A, const __half* __restrict__ Wh,
    __half* __restrict__ C16, const float* __restrict__ disv, int M, int K,
    const float* __restrict__ stats, const float* __restrict__ gam,
    const float* __restrict__ bt)
{
    gemm_body<BN>(blockIdx.x, A, Wh, C16, disv, M, K, stats, gam, bt);
}

// Fused CSR scatter + layer-1 GEMM (independent work, interleaved block stripe)
__global__ __launch_bounds__(256) void k_scatter_gemm1(
    const int* __restrict__ ei, int* __restrict__ cursor, int* __restrict__ csr_src,
    int E, int ngemm,
    const float* __restrict__ A, const __half* __restrict__ Wh,
    __half* __restrict__ C16, const float* __restrict__ disv, int M)
{
    int b = blockIdx.x;
    bool is_gemm;
    int id;
    if (b < 2 * ngemm) { is_gemm = (b & 1); id = b >> 1; }
    else               { is_gemm = false;   id = b - ngemm; }
    if (!is_gemm) {
        int e = id * 256 + threadIdx.x;
        if (e < E) {
            int src = __ldg(ei + e);
            int dst = __ldg(ei + E + e);
            int pos = atomicAdd(&cursor[dst], 1);
            csr_src[pos] = src;
        }
        return;
    }
    gemm_body<128>(id, A, Wh, C16, disv, M, 256, nullptr, nullptr, nullptr);
}

// ---------------------------------------------------------------------------
// CSR gather on fp16 prescaled rows + fused BN statistics (4-edge unroll).
// Output agg is fp32.
// ---------------------------------------------------------------------------
template <int F>
__global__ __launch_bounds__(256) void k_gather16(
    const int* __restrict__ rowptr, const int* __restrict__ deg,
    const int* __restrict__ csr_src, const __half* __restrict__ h16,
    const float* __restrict__ dis, const float* __restrict__ bias,
    float* __restrict__ agg, float* __restrict__ stats, int N)
{
    constexpr int G = F / 8;
    __shared__ float ssum[F];
    __shared__ float ssq[F];
    const int tid = threadIdx.x;
    if (tid < F) { ssum[tid] = 0.0f; ssq[tid] = 0.0f; }
    __syncthreads();

    int t    = blockIdx.x * 256 + tid;
    int node = t / G;
    int j    = t - node * G;
    const bool valid = node < N;
    const int cn = valid ? node : 0;

    int start = __ldg(rowptr + cn);
    int cnt   = valid ? __ldg(deg + cn) : 0;
    const __half* base = h16 + j * 8;

    float a[8];
#pragma unroll
    for (int q = 0; q < 8; q++) a[q] = 0.0f;

    auto addv = [&](uint4 v) {
        const __half2* hv = (const __half2*)&v;
#pragma unroll
        for (int q = 0; q < 4; q++) {
            float2 f = __half22float2(hv[q]);
            a[2 * q]     += f.x;
            a[2 * q + 1] += f.y;
        }
    };

    int p = 0;
    for (; p + 4 <= cnt; p += 4) {
        int s0 = __ldg(csr_src + start + p);
        int s1 = __ldg(csr_src + start + p + 1);
        int s2 = __ldg(csr_src + start + p + 2);
        int s3 = __ldg(csr_src + start + p + 3);
        uint4 v0 = __ldg((const uint4*)(base + (size_t)s0 * F));
        uint4 v1 = __ldg((const uint4*)(base + (size_t)s1 * F));
        uint4 v2 = __ldg((const uint4*)(base + (size_t)s2 * F));
        uint4 v3 = __ldg((const uint4*)(base + (size_t)s3 * F));
        addv(v0); addv(v1); addv(v2); addv(v3);
    }
    for (; p < cnt; p++) {
        int s = __ldg(csr_src + start + p);
        addv(__ldg((const uint4*)(base + (size_t)s * F)));
    }
    if (valid) addv(__ldg((const uint4*)(base + (size_t)cn * F)));  // self-loop

    float d = valid ? __ldg(dis + cn) : 0.0f;
    float4 b0 = __ldg((const float4*)(bias + j * 8));
    float4 b1 = __ldg((const float4*)(bias + j * 8) + 1);
    float r[8];
    r[0] = fmaf(d, a[0], b0.x); r[1] = fmaf(d, a[1], b0.y);
    r[2] = fmaf(d, a[2], b0.z); r[3] = fmaf(d, a[3], b0.w);
    r[4] = fmaf(d, a[4], b1.x); r[5] = fmaf(d, a[5], b1.y);
    r[6] = fmaf(d, a[6], b1.z); r[7] = fmaf(d, a[7], b1.w);

    if (valid) {
        float4* o = (float4*)(agg + (size_t)node * F + j * 8);
        o[0] = make_float4(r[0], r[1], r[2], r[3]);
        o[1] = make_float4(r[4], r[5], r[6], r[7]);
    } else {
#pragma unroll
        for (int q = 0; q < 8; q++) r[q] = 0.0f;
    }

    float s2v[8];
#pragma unroll
    for (int q = 0; q < 8; q++) s2v[q] = r[q] * r[q];
#pragma unroll
    for (int o = 16; o >= G; o >>= 1) {
#pragma unroll
        for (int q = 0; q < 8; q++) {
            r[q]   += __shfl_xor_sync(0xFFFFFFFFu, r[q],   o);
            s2v[q] += __shfl_xor_sync(0xFFFFFFFFu, s2v[q], o);
        }
    }
    int lane = tid & 31;
    if (lane < G) {
#pragma unroll
        for (int q = 0; q < 8; q++) {
            atomicAdd(&ssum[lane * 8 + q], r[q]);
            atomicAdd(&ssq[lane * 8 + q],  s2v[q]);
        }
    }
    __syncthreads();
    if (tid < F) {
        atomicAdd(&stats[tid],     ssum[tid]);
        atomicAdd(&stats[F + tid], ssq[tid]);
    }
}

// ---------------------------------------------------------------------------
// Final FC with in-kernel BN finalize + fused BN+ReLU (fp32 input)
// ---------------------------------------------------------------------------
__global__ void k_final_fc(const float* __restrict__ h, const float* __restrict__ stats,
                           const float* __restrict__ gam, const float* __restrict__ bt,
                           const float* __restrict__ W, const float* __restrict__ b,
                           float* __restrict__ out, int N)
{
    __shared__ float sc_s[32], sh_s[32];
    int tid = threadIdx.x;
    if (tid < 32) {
        float inv_n = 1.0f / (float)N;
        float mu  = stats[tid] * inv_n;
        float var = fmaxf(stats[32 + tid] * inv_n - mu * mu, 0.0f);
        float sc  = gam[tid] * rsqrtf(var + 1e-5f);
        sc_s[tid] = sc;
        sh_s[tid] = bt[tid] - mu * sc;
    }
    __syncthreads();
    int lane = tid & 31;
    int node = (blockIdx.x * blockDim.x + tid) >> 5;
    if (node >= N) return;
    float v = fmaxf(fmaf(h[(size_t)node * 32 + lane], sc_s[lane], sh_s[lane]), 0.0f)
              * __ldg(W + lane);
#pragma unroll
    for (int o = 16; o; o >>= 1) v += __shfl_down_sync(0xFFFFFFFFu, v, o);
    if (lane == 0) out[node] = v + __ldg(b);
}

// ---------------------------------------------------------------------------
static inline int cdiv(long long a, long long b) { return (int)((a + b - 1) / b); }

extern "C" void kernel_launch(void* const* d_in, const int* in_sizes, int n_in,
                              void* d_out, int out_size)
{
    const float* x   = (const float*)d_in[0];
    const int*   ei  = (const int*)d_in[1];
    const float* W1  = (const float*)d_in[2];
    const float* b1  = (const float*)d_in[3];
    const float* g1  = (const float*)d_in[4];
    const float* bt1 = (const float*)d_in[5];
    const float* W2  = (const float*)d_in[6];
    const float* b2  = (const float*)d_in[7];
    const float* g2  = (const float*)d_in[8];
    const float* bt2 = (const float*)d_in[9];
    const float* W3  = (const float*)d_in[10];
    const float* b3  = (const float*)d_in[11];
    const float* g3  = (const float*)d_in[12];
    const float* bt3 = (const float*)d_in[13];
    const float* Wfc = (const float*)d_in[14];
    const float* bfc = (const float*)d_in[15];
    float* out = (float*)d_out;

    const int N = in_sizes[0] / 256;
    const int E = in_sizes[1] / 2;

    float *agg, *dis, *stats;
    __half *h16, *whi;
    int *deg, *rowptr, *cursor, *bsum, *csr;
    cudaGetSymbolAddress((void**)&agg,    g_agg);
    cudaGetSymbolAddress((void**)&h16,    g_h16);
    cudaGetSymbolAddress((void**)&dis,    g_dis);
    cudaGetSymbolAddress((void**)&deg,    g_deg);
    cudaGetSymbolAddress((void**)&rowptr, g_rowptr);
    cudaGetSymbolAddress((void**)&cursor, g_cursor);
    cudaGetSymbolAddress((void**)&bsum,   g_bsum);
    cudaGetSymbolAddress((void**)&csr,    g_csr_src);
    cudaGetSymbolAddress((void**)&stats,  g_stats);
    cudaGetSymbolAddress((void**)&whi,    g_whi);

    const int nsc   = cdiv(E, 256);
    const int nw    = cdiv(WTOT, 256);
    const int nb    = cdiv(N, 1024);
    const int ngemm = cdiv(N, 64);

    // ---- prologue: degree count + weight round, scan(+dis), scatter+GEMM1 ----
    cudaMemsetAsync(deg, 0, (size_t)N * sizeof(int));
    k_pro1<<<nsc + nw, 256>>>(ei, deg, E, nsc, W1, W2, W3, whi);
    k_scan_block<<<nb, 1024>>>(deg, rowptr, bsum, dis, N);
    k_scan_add2<<<cdiv(N, 256), 256>>>(rowptr, cursor, bsum, stats, nb, N);
    k_scatter_gemm1<<<ngemm + nsc, 256>>>(ei, cursor, csr, E, ngemm,
                                          x, whi, h16, dis, N);

    // ================= Layer 1 gather (F=128) =================
    k_gather16<128><<<cdiv((long long)N * 16, 256), 256>>>(
        rowptr, deg, csr, h16, dis, b1, agg, stats, N);

    // ================= Layer 2: 128 -> 64 =================
    k_mma_gemm<64><<<ngemm, 256>>>(agg, whi + W2_OFF, h16, dis, N, 128,
                                   stats, g1, bt1);
    k_gather16<64><<<cdiv((long long)N * 8, 256), 256>>>(
        rowptr, deg, csr, h16, dis, b2, agg, stats + ST2, N);

    // ================= Layer 3: 64 -> 32 =================
    k_mma_gemm<32><<<ngemm, 256>>>(agg, whi + W3_OFF, h16, dis, N, 64,
                                   stats + ST2, g2, bt2);
    k_gather16<32><<<cdiv((long long)N * 4, 256), 256>>>(
        rowptr, deg, csr, h16, dis, b3, agg, stats + ST3, N);

    // ================= Final FC: 32 -> 1 (in-kernel BN + ReLU) =================
    k_final_fc<<<cdiv((long long)N * 32, 256), 256>>>(agg, stats + ST3, g3, bt3,
                                                      Wfc, bfc, out, N);
}